// round 1
// baseline (speedup 1.0000x reference)
#include <cuda_runtime.h>

#define S_LEN 1024
#define BATCH 4
#define HID   1024
#define NHEAD 16
#define HDIM  64
#define NH    (BATCH*NHEAD)     // 64 total heads
#define HS    (S_LEN*HDIM)      // 65536 floats per head

// Scratch for projected Q/K/V in head-major layout [n][s][d]
__device__ float g_q[NH*HS];
__device__ float g_k[NH*HS];
__device__ float g_v[NH*HS];

// ------------------------------------------------------------------
// QKV GEMM: out[n][s][d] = hidden(S*B x H) @ W^T + bias, scattered to
// attention layout.  M=4096 (m = s*4+b), N=1024 (col = h*64+d), K=1024.
// ------------------------------------------------------------------
#define BM 128
#define BN 128
#define BK 16
#define PA 129   // padded stride for As[k][m]
#define PW 132   // padded stride for Ws[k][n]

__global__ __launch_bounds__(256)
void qkv_gemm(const float* __restrict__ A, const float* __restrict__ W,
              const float* __restrict__ bias, int which)
{
    __shared__ float As[BK*PA];
    __shared__ float Ws[BK*PW];
    float* out = (which == 0) ? g_q : ((which == 1) ? g_k : g_v);

    const int tid = threadIdx.x;
    const int m0  = blockIdx.y * BM;
    const int n0  = blockIdx.x * BN;
    const int ty  = tid >> 4;   // 0..15
    const int tx  = tid & 15;   // 0..15

    float acc[8][8];
#pragma unroll
    for (int i = 0; i < 8; i++)
#pragma unroll
        for (int j = 0; j < 8; j++) acc[i][j] = 0.f;

    for (int k0 = 0; k0 < HID; k0 += BK) {
#pragma unroll
        for (int ld = 0; ld < 2; ld++) {
            int e  = tid + ld * 256;      // 0..511
            int r  = e >> 2;              // 0..127
            int c4 = e & 3;               // 0..3 (float4 within 16 cols)
            float4 a = *(const float4*)(A + (size_t)(m0 + r) * HID + k0 + c4 * 4);
            As[(c4*4+0)*PA + r] = a.x;
            As[(c4*4+1)*PA + r] = a.y;
            As[(c4*4+2)*PA + r] = a.z;
            As[(c4*4+3)*PA + r] = a.w;
            float4 w4 = *(const float4*)(W + (size_t)(n0 + r) * HID + k0 + c4 * 4);
            Ws[(c4*4+0)*PW + r] = w4.x;
            Ws[(c4*4+1)*PW + r] = w4.y;
            Ws[(c4*4+2)*PW + r] = w4.z;
            Ws[(c4*4+3)*PW + r] = w4.w;
        }
        __syncthreads();

#pragma unroll
        for (int kk = 0; kk < BK; kk++) {
            float ra[8], rb[8];
#pragma unroll
            for (int i = 0; i < 8; i++) ra[i] = As[kk*PA + ty*8 + i];
            float4 b0 = *(const float4*)&Ws[kk*PW + tx*8];
            float4 b1 = *(const float4*)&Ws[kk*PW + tx*8 + 4];
            rb[0]=b0.x; rb[1]=b0.y; rb[2]=b0.z; rb[3]=b0.w;
            rb[4]=b1.x; rb[5]=b1.y; rb[6]=b1.z; rb[7]=b1.w;
#pragma unroll
            for (int i = 0; i < 8; i++)
#pragma unroll
                for (int j = 0; j < 8; j++)
                    acc[i][j] += ra[i] * rb[j];
        }
        __syncthreads();
    }

    // Epilogue: add bias, scatter to [n=b*16+h][s][d]
#pragma unroll
    for (int i = 0; i < 8; i++) {
        int m = m0 + ty*8 + i;
        int s = m >> 2;
        int b = m & 3;
        int col0 = n0 + tx*8;
        int h  = col0 >> 6;        // 8 | 64 so constant over j
        int d0 = col0 & 63;
        float* dst = out + ((size_t)(b*NHEAD + h) * S_LEN + s) * HDIM + d0;
        float4 o0, o1;
        o0.x = acc[i][0] + bias[col0+0];
        o0.y = acc[i][1] + bias[col0+1];
        o0.z = acc[i][2] + bias[col0+2];
        o0.w = acc[i][3] + bias[col0+3];
        o1.x = acc[i][4] + bias[col0+4];
        o1.y = acc[i][5] + bias[col0+5];
        o1.z = acc[i][6] + bias[col0+6];
        o1.w = acc[i][7] + bias[col0+7];
        *(float4*)(dst)     = o0;
        *(float4*)(dst + 4) = o1;
    }
}

// ------------------------------------------------------------------
// Fused attention: one block per (head n, 64-query tile).
// Online softmax over 16 key tiles of 64.  256 threads.
// smem: qs[64][68], kst[64][68] (transposed [d][t]), vs[64][68],
//       ps[64][68], rowm/rowl/rowf[64], mk[64]
// ------------------------------------------------------------------
#define PADR 68
#define SMEM_FLOATS (4*64*PADR + 4*64)
#define SMEM_BYTES  (SMEM_FLOATS*4)

__global__ __launch_bounds__(256)
void attn_kernel(const float* __restrict__ mask, float* __restrict__ out)
{
    extern __shared__ float sm[];
    float* qs   = sm;                   // [r][d]
    float* kst  = qs  + 64*PADR;        // [d][t]
    float* vs   = kst + 64*PADR;        // [t][d]
    float* ps   = vs  + 64*PADR;        // [r][t]
    float* rowm = ps  + 64*PADR;
    float* rowl = rowm + 64;
    float* rowf = rowl + 64;
    float* mk   = rowf + 64;

    const int n   = blockIdx.x;         // head index 0..63
    const int qt  = blockIdx.y;         // query tile 0..15
    const int tid = threadIdx.x;
    const float scale = 0.125f;         // 1/sqrt(64)

    // load Q tile (scaled)
    const float* qg = g_q + (size_t)n*HS + qt*64*HDIM;
#pragma unroll
    for (int ld = 0; ld < 4; ld++) {
        int e  = tid + ld*256;          // 0..1023
        int r  = e >> 4;
        int c4 = e & 15;
        float4 a = *(const float4*)(qg + r*HDIM + c4*4);
        a.x *= scale; a.y *= scale; a.z *= scale; a.w *= scale;
        *(float4*)&qs[r*PADR + c4*4] = a;
    }
    if (tid < 64) { rowm[tid] = -1e30f; rowl[tid] = 0.f; }

    float4 acc[4];
#pragma unroll
    for (int i = 0; i < 4; i++) acc[i] = make_float4(0.f,0.f,0.f,0.f);

    const int rA = (tid >> 4) << 2;     // row group base (0..60)
    const int tA = (tid & 15) << 2;     // t / d column base (0..60)

    for (int kt = 0; kt < 16; kt++) {
        __syncthreads();   // prev AV done before overwriting k/v
        const float* kg = g_k + (size_t)n*HS + kt*64*HDIM;
        const float* vg = g_v + (size_t)n*HS + kt*64*HDIM;
#pragma unroll
        for (int ld = 0; ld < 4; ld++) {
            int e  = tid + ld*256;
            int t  = e >> 4;
            int c4 = e & 15;
            float4 kk4 = *(const float4*)(kg + t*HDIM + c4*4);
            kst[(c4*4+0)*PADR + t] = kk4.x;
            kst[(c4*4+1)*PADR + t] = kk4.y;
            kst[(c4*4+2)*PADR + t] = kk4.z;
            kst[(c4*4+3)*PADR + t] = kk4.w;
            float4 vv4 = *(const float4*)(vg + t*HDIM + c4*4);
            *(float4*)&vs[t*PADR + c4*4] = vv4;
        }
        if (tid < 64) mk[tid] = mask[(size_t)n*S_LEN + kt*64 + tid];
        __syncthreads();

        // ---- Phase A: scores 4x4 per thread ----
        float sc[4][4];
#pragma unroll
        for (int i = 0; i < 4; i++)
#pragma unroll
            for (int j = 0; j < 4; j++) sc[i][j] = 0.f;

#pragma unroll
        for (int d = 0; d < 64; d += 4) {
            float aq[4][4], bk4[4][4];
#pragma unroll
            for (int i = 0; i < 4; i++) {
                float4 a = *(const float4*)&qs[(rA+i)*PADR + d];
                aq[i][0]=a.x; aq[i][1]=a.y; aq[i][2]=a.z; aq[i][3]=a.w;
            }
#pragma unroll
            for (int dd = 0; dd < 4; dd++) {
                float4 b4 = *(const float4*)&kst[(d+dd)*PADR + tA];
                bk4[dd][0]=b4.x; bk4[dd][1]=b4.y; bk4[dd][2]=b4.z; bk4[dd][3]=b4.w;
            }
#pragma unroll
            for (int i = 0; i < 4; i++)
#pragma unroll
                for (int j = 0; j < 4; j++)
#pragma unroll
                    for (int dd = 0; dd < 4; dd++)
                        sc[i][j] += aq[i][dd] * bk4[dd][j];
        }
#pragma unroll
        for (int i = 0; i < 4; i++) {
            float4 o;
            o.x = sc[i][0] + mk[tA+0];
            o.y = sc[i][1] + mk[tA+1];
            o.z = sc[i][2] + mk[tA+2];
            o.w = sc[i][3] + mk[tA+3];
            *(float4*)&ps[(rA+i)*PADR + tA] = o;
        }
        __syncthreads();

        // ---- Phase B: online softmax update (64 row threads) ----
        if (tid < 64) {
            int r = tid;
            float mOld = rowm[r];
            float mNew = mOld;
#pragma unroll 8
            for (int t = 0; t < 64; t++) mNew = fmaxf(mNew, ps[r*PADR + t]);
            float f = __expf(mOld - mNew);
            float ssum = 0.f;
#pragma unroll 8
            for (int t = 0; t < 64; t++) {
                float p = __expf(ps[r*PADR + t] - mNew);
                ps[r*PADR + t] = p;
                ssum += p;
            }
            rowl[r] = rowl[r]*f + ssum;
            rowm[r] = mNew;
            rowf[r] = f;
        }
        __syncthreads();

        // ---- Phase C: AV accumulate, 4 rows x 4 dims per thread ----
        float f4[4];
#pragma unroll
        for (int i = 0; i < 4; i++) f4[i] = rowf[rA+i];
#pragma unroll
        for (int i = 0; i < 4; i++) {
            acc[i].x *= f4[i]; acc[i].y *= f4[i];
            acc[i].z *= f4[i]; acc[i].w *= f4[i];
        }
#pragma unroll 4
        for (int t = 0; t < 64; t++) {
            float4 vv = *(const float4*)&vs[t*PADR + tA];
#pragma unroll
            for (int i = 0; i < 4; i++) {
                float p = ps[(rA+i)*PADR + t];
                acc[i].x += p * vv.x;
                acc[i].y += p * vv.y;
                acc[i].z += p * vv.z;
                acc[i].w += p * vv.w;
            }
        }
    }

    // ---- epilogue: normalize and write (S,B,H) ----
    const int b = n >> 4;
    const int h = n & 15;
#pragma unroll
    for (int i = 0; i < 4; i++) {
        int s = qt*64 + rA + i;
        float inv = 1.f / rowl[rA+i];
        float4 o;
        o.x = acc[i].x * inv; o.y = acc[i].y * inv;
        o.z = acc[i].z * inv; o.w = acc[i].w * inv;
        *(float4*)(out + (size_t)s*(BATCH*HID) + b*HID + h*HDIM + tA) = o;
    }
}

// ------------------------------------------------------------------
extern "C" void kernel_launch(void* const* d_in, const int* in_sizes, int n_in,
                              void* d_out, int out_size)
{
    const float* hs   = (const float*)d_in[0];
    const float* mask = (const float*)d_in[1];
    const float* Wq   = (const float*)d_in[2];
    const float* bq   = (const float*)d_in[3];
    const float* Wk   = (const float*)d_in[4];
    const float* bk   = (const float*)d_in[5];
    const float* Wv   = (const float*)d_in[6];
    const float* bv   = (const float*)d_in[7];
    float* out = (float*)d_out;

    dim3 gg(HID/BN, (S_LEN*BATCH)/BM);   // (8, 32)
    qkv_gemm<<<gg, 256>>>(hs, Wq, bq, 0);
    qkv_gemm<<<gg, 256>>>(hs, Wk, bk, 1);
    qkv_gemm<<<gg, 256>>>(hs, Wv, bv, 2);

    cudaFuncSetAttribute(attn_kernel, cudaFuncAttributeMaxDynamicSharedMemorySize,
                         SMEM_BYTES);
    attn_kernel<<<dim3(NH, 16), 256, SMEM_BYTES>>>(mask, out);
}

// round 3
// speedup vs baseline: 1.3728x; 1.3728x over previous
#include <cuda_runtime.h>
#include <cuda_bf16.h>
#include <cstdint>

#define S_LEN 1024
#define BATCH 4
#define HID   1024
#define NHEAD 16
#define HDIM  64
#define NH    (BATCH*NHEAD)     // 64 heads
#define MTOT  (S_LEN*BATCH)     // 4096
#define NTOT  (3*HID)           // 3072 (q|k|v stacked)

// split-bf16 GEMM operands
__device__ unsigned short g_Ahi[MTOT*HID], g_Alo[MTOT*HID];
__device__ unsigned short g_Whi[NTOT*HID], g_Wlo[NTOT*HID];
// projected tensors, split bf16.  q,k: [head][s][d]   v: [head][d][s] (transposed)
__device__ unsigned short g_qhi[NH*S_LEN*HDIM], g_qlo[NH*S_LEN*HDIM];
__device__ unsigned short g_khi[NH*S_LEN*HDIM], g_klo[NH*S_LEN*HDIM];
__device__ unsigned short g_vhi[NH*S_LEN*HDIM], g_vlo[NH*S_LEN*HDIM];

// ---------------- mma.sync helper (sm_80+ baseline ISA) ----------------
__device__ __forceinline__ void mma16816(float* c, const uint32_t* a, const uint32_t* b) {
    asm volatile("mma.sync.aligned.m16n8k16.row.col.f32.bf16.bf16.f32 "
        "{%0,%1,%2,%3},{%4,%5,%6,%7},{%8,%9},{%0,%1,%2,%3};"
        : "+f"(c[0]), "+f"(c[1]), "+f"(c[2]), "+f"(c[3])
        : "r"(a[0]), "r"(a[1]), "r"(a[2]), "r"(a[3]), "r"(b[0]), "r"(b[1]));
}

__device__ __forceinline__ void split2(float x, float y, uint32_t& hi, uint32_t& lo) {
    __nv_bfloat16 hx = __float2bfloat16(x);
    __nv_bfloat16 hy = __float2bfloat16(y);
    __nv_bfloat16 lx = __float2bfloat16(x - __bfloat162float(hx));
    __nv_bfloat16 ly = __float2bfloat16(y - __bfloat162float(hy));
    hi = (uint32_t)__bfloat16_as_ushort(hx) | ((uint32_t)__bfloat16_as_ushort(hy) << 16);
    lo = (uint32_t)__bfloat16_as_ushort(lx) | ((uint32_t)__bfloat16_as_ushort(ly) << 16);
}

// ---------------- split-bf16 conversion ----------------
__global__ __launch_bounds__(256)
void cvt_split(const float* __restrict__ src, unsigned short* __restrict__ hi,
               unsigned short* __restrict__ lo, int n4)
{
    int i = blockIdx.x * blockDim.x + threadIdx.x;
    if (i >= n4) return;
    float4 x = ((const float4*)src)[i];
    ushort4 h, l;
    __nv_bfloat16 b;
    b = __float2bfloat16(x.x); h.x = __bfloat16_as_ushort(b);
    l.x = __bfloat16_as_ushort(__float2bfloat16(x.x - __bfloat162float(b)));
    b = __float2bfloat16(x.y); h.y = __bfloat16_as_ushort(b);
    l.y = __bfloat16_as_ushort(__float2bfloat16(x.y - __bfloat162float(b)));
    b = __float2bfloat16(x.z); h.z = __bfloat16_as_ushort(b);
    l.z = __bfloat16_as_ushort(__float2bfloat16(x.z - __bfloat162float(b)));
    b = __float2bfloat16(x.w); h.w = __bfloat16_as_ushort(b);
    l.w = __bfloat16_as_ushort(__float2bfloat16(x.w - __bfloat162float(b)));
    ((ushort4*)hi)[i] = h;
    ((ushort4*)lo)[i] = l;
}

// ---------------- QKV GEMM via mma.sync ----------------
// C[4096 x 3072] = A @ W^T (+bias), tile 128x128, BK=32, 8 warps of m64n32.
#define GSTR 40   // smem row stride (bf16 elems): 80B, conflict-free pattern

__global__ __launch_bounds__(256)
void qkv_mma(const float* __restrict__ bq, const float* __restrict__ bk,
             const float* __restrict__ bv)
{
    __shared__ unsigned short Ah[128*GSTR], Al[128*GSTR];
    __shared__ unsigned short Wh[128*GSTR], Wl[128*GSTR];

    const int tid = threadIdx.x, lane = tid & 31, wid = tid >> 5;
    const int wm = wid >> 2, wn = wid & 3;        // warp tile: m64 x n32
    const int g = lane >> 2, tg = lane & 3;
    const int m0 = blockIdx.y * 128, c0 = blockIdx.x * 128;
    const int r = tid & 127, half = tid >> 7;

    float acc[4][4][4];
#pragma unroll
    for (int i = 0; i < 4; i++)
#pragma unroll
        for (int j = 0; j < 4; j++)
#pragma unroll
            for (int k = 0; k < 4; k++) acc[i][j][k] = 0.f;

    const unsigned short* gAh = g_Ahi + (size_t)(m0 + r) * HID + half * 16;
    const unsigned short* gAl = g_Alo + (size_t)(m0 + r) * HID + half * 16;
    const unsigned short* gWh = g_Whi + (size_t)(c0 + r) * HID + half * 16;
    const unsigned short* gWl = g_Wlo + (size_t)(c0 + r) * HID + half * 16;
    unsigned short* sAh = Ah + r * GSTR + half * 16;
    unsigned short* sAl = Al + r * GSTR + half * 16;
    unsigned short* sWh = Wh + r * GSTR + half * 16;
    unsigned short* sWl = Wl + r * GSTR + half * 16;

    for (int k0 = 0; k0 < HID; k0 += 32) {
        if (k0) __syncthreads();
        *(uint4*)(sAh)     = *(const uint4*)(gAh + k0);
        *(uint4*)(sAh + 8) = *(const uint4*)(gAh + k0 + 8);
        *(uint4*)(sAl)     = *(const uint4*)(gAl + k0);
        *(uint4*)(sAl + 8) = *(const uint4*)(gAl + k0 + 8);
        *(uint4*)(sWh)     = *(const uint4*)(gWh + k0);
        *(uint4*)(sWh + 8) = *(const uint4*)(gWh + k0 + 8);
        *(uint4*)(sWl)     = *(const uint4*)(gWl + k0);
        *(uint4*)(sWl + 8) = *(const uint4*)(gWl + k0 + 8);
        __syncthreads();

#pragma unroll
        for (int ks = 0; ks < 2; ks++) {
            const int kb = ks * 16 + 2 * tg;
            uint32_t ah[4][4], al[4][4];
#pragma unroll
            for (int mi = 0; mi < 4; mi++) {
                int rr = wm * 64 + mi * 16 + g;
                ah[mi][0] = *(const uint32_t*)&Ah[rr * GSTR + kb];
                ah[mi][1] = *(const uint32_t*)&Ah[(rr + 8) * GSTR + kb];
                ah[mi][2] = *(const uint32_t*)&Ah[rr * GSTR + kb + 8];
                ah[mi][3] = *(const uint32_t*)&Ah[(rr + 8) * GSTR + kb + 8];
                al[mi][0] = *(const uint32_t*)&Al[rr * GSTR + kb];
                al[mi][1] = *(const uint32_t*)&Al[(rr + 8) * GSTR + kb];
                al[mi][2] = *(const uint32_t*)&Al[rr * GSTR + kb + 8];
                al[mi][3] = *(const uint32_t*)&Al[(rr + 8) * GSTR + kb + 8];
            }
#pragma unroll
            for (int ni = 0; ni < 4; ni++) {
                int nn = wn * 32 + ni * 8 + g;
                uint32_t bh[2], bl[2];
                bh[0] = *(const uint32_t*)&Wh[nn * GSTR + kb];
                bh[1] = *(const uint32_t*)&Wh[nn * GSTR + kb + 8];
                bl[0] = *(const uint32_t*)&Wl[nn * GSTR + kb];
                bl[1] = *(const uint32_t*)&Wl[nn * GSTR + kb + 8];
#pragma unroll
                for (int mi = 0; mi < 4; mi++) {
                    mma16816(acc[mi][ni], ah[mi], bh);
                    mma16816(acc[mi][ni], al[mi], bh);
                    mma16816(acc[mi][ni], ah[mi], bl);
                }
            }
        }
    }

    // epilogue: bias (+0.125 scale for Q), split-bf16, scatter
    const int which = c0 >> 10;
    const float* bias = (which == 0) ? bq : ((which == 1) ? bk : bv);
    const float qsc = (which == 0) ? 0.125f : 1.0f;

#pragma unroll
    for (int mi = 0; mi < 4; mi++) {
#pragma unroll
        for (int ni = 0; ni < 4; ni++) {
            int colE = c0 + wn * 32 + ni * 8 + 2 * tg;
            int bcol = colE & 1023;
            float b0f = bias[bcol], b1f = bias[bcol + 1];
            int hh = (colE >> 6) & 15, dd = colE & 63;
#pragma unroll
            for (int hr = 0; hr < 2; hr++) {
                int row = m0 + wm * 64 + mi * 16 + g + hr * 8;
                int s = row >> 2, b = row & 3;
                float x = (acc[mi][ni][hr * 2 + 0] + b0f) * qsc;
                float y = (acc[mi][ni][hr * 2 + 1] + b1f) * qsc;
                uint32_t hi, lo;
                split2(x, y, hi, lo);
                int head = b * NHEAD + hh;
                if (which == 0) {
                    size_t idx = ((size_t)head * S_LEN + s) * HDIM + dd;
                    *(uint32_t*)&g_qhi[idx] = hi;
                    *(uint32_t*)&g_qlo[idx] = lo;
                } else if (which == 1) {
                    size_t idx = ((size_t)head * S_LEN + s) * HDIM + dd;
                    *(uint32_t*)&g_khi[idx] = hi;
                    *(uint32_t*)&g_klo[idx] = lo;
                } else {
                    size_t idx = ((size_t)head * HDIM + dd) * S_LEN + s;
                    g_vhi[idx]         = (unsigned short)(hi & 0xffff);
                    g_vhi[idx + S_LEN] = (unsigned short)(hi >> 16);
                    g_vlo[idx]         = (unsigned short)(lo & 0xffff);
                    g_vlo[idx + S_LEN] = (unsigned short)(lo >> 16);
                }
            }
        }
    }
}

// ---------------- fused attention via mma.sync ----------------
// block = (head, 64-query tile); 8 warps as m-tile wm(0..3) x n-half wn(0..1)
#define PQ 72   // bf16 smem stride
#define PS 68   // fp32 smem stride
#define OFF_QH 0
#define OFF_QL (OFF_QH + 64*PQ*2)
#define OFF_KH (OFF_QL + 64*PQ*2)
#define OFF_KL (OFF_KH + 64*PQ*2)
#define OFF_VH (OFF_KL + 64*PQ*2)
#define OFF_VL (OFF_VH + 64*PQ*2)
#define OFF_PH (OFF_VL + 64*PQ*2)
#define OFF_PL (OFF_PH + 64*PQ*2)
#define OFF_PS (OFF_PL + 64*PQ*2)
#define OFF_RM (OFF_PS + 64*PS*4)
#define OFF_RL (OFF_RM + 64*4)
#define OFF_RF (OFF_RL + 64*4)
#define OFF_MK (OFF_RF + 64*4)
#define SMEM_ATTN (OFF_MK + 64*4)

__global__ __launch_bounds__(256)
void attn_mma(const float* __restrict__ mask, float* __restrict__ out)
{
    extern __shared__ char smc[];
    unsigned short* qh = (unsigned short*)(smc + OFF_QH);
    unsigned short* ql = (unsigned short*)(smc + OFF_QL);
    unsigned short* kh = (unsigned short*)(smc + OFF_KH);
    unsigned short* kl = (unsigned short*)(smc + OFF_KL);
    unsigned short* vh = (unsigned short*)(smc + OFF_VH);
    unsigned short* vl = (unsigned short*)(smc + OFF_VL);
    unsigned short* ph = (unsigned short*)(smc + OFF_PH);
    unsigned short* pl = (unsigned short*)(smc + OFF_PL);
    float* ps   = (float*)(smc + OFF_PS);
    float* rowm = (float*)(smc + OFF_RM);
    float* rowl = (float*)(smc + OFF_RL);
    float* rowf = (float*)(smc + OFF_RF);
    float* mk   = (float*)(smc + OFF_MK);

    const int n = blockIdx.x, qt = blockIdx.y;
    const int tid = threadIdx.x, lane = tid & 31, wid = tid >> 5;
    const int wm = wid >> 1, wn = wid & 1;       // m16 x n32 per warp
    const int g = lane >> 2, tg = lane & 3;
    const int lr = tid & 63, seg = tid >> 6;     // tile-load mapping

    // load Q (split bf16, already scaled by 1/8)
    {
        const unsigned short* gq = g_qhi + ((size_t)n * S_LEN + qt * 64) * HDIM;
        const unsigned short* gl = g_qlo + ((size_t)n * S_LEN + qt * 64) * HDIM;
        *(uint4*)&qh[lr*PQ + seg*16]     = *(const uint4*)(gq + lr*64 + seg*16);
        *(uint4*)&qh[lr*PQ + seg*16 + 8] = *(const uint4*)(gq + lr*64 + seg*16 + 8);
        *(uint4*)&ql[lr*PQ + seg*16]     = *(const uint4*)(gl + lr*64 + seg*16);
        *(uint4*)&ql[lr*PQ + seg*16 + 8] = *(const uint4*)(gl + lr*64 + seg*16 + 8);
    }
    if (tid < 64) { rowm[tid] = -1e30f; rowl[tid] = 0.f; }

    float oacc[4][4];
#pragma unroll
    for (int i = 0; i < 4; i++)
#pragma unroll
        for (int j = 0; j < 4; j++) oacc[i][j] = 0.f;

    for (int kt = 0; kt < 16; kt++) {
        __syncthreads();
        // load K tile [key][d], V tile [d][key] (pre-transposed in gmem)
        {
            const unsigned short* a = g_khi + ((size_t)n * S_LEN + kt * 64) * HDIM;
            const unsigned short* b = g_klo + ((size_t)n * S_LEN + kt * 64) * HDIM;
            const unsigned short* c = g_vhi + (size_t)n * S_LEN * HDIM + (size_t)lr * S_LEN + kt * 64;
            const unsigned short* d = g_vlo + (size_t)n * S_LEN * HDIM + (size_t)lr * S_LEN + kt * 64;
            int so = lr*PQ + seg*16;
            *(uint4*)&kh[so]     = *(const uint4*)(a + lr*64 + seg*16);
            *(uint4*)&kh[so + 8] = *(const uint4*)(a + lr*64 + seg*16 + 8);
            *(uint4*)&kl[so]     = *(const uint4*)(b + lr*64 + seg*16);
            *(uint4*)&kl[so + 8] = *(const uint4*)(b + lr*64 + seg*16 + 8);
            *(uint4*)&vh[so]     = *(const uint4*)(c + seg*16);
            *(uint4*)&vh[so + 8] = *(const uint4*)(c + seg*16 + 8);
            *(uint4*)&vl[so]     = *(const uint4*)(d + seg*16);
            *(uint4*)&vl[so + 8] = *(const uint4*)(d + seg*16 + 8);
        }
        if (tid < 64) mk[tid] = mask[(size_t)n * S_LEN + kt * 64 + tid];
        __syncthreads();

        // ---- scores: S = Q K^T (split bf16, 3 terms) ----
        float sacc[4][4];
#pragma unroll
        for (int i = 0; i < 4; i++)
#pragma unroll
            for (int j = 0; j < 4; j++) sacc[i][j] = 0.f;

#pragma unroll
        for (int ks = 0; ks < 4; ks++) {
            const int kb = ks * 16 + 2 * tg;
            const int rq = wm * 16 + g;
            uint32_t ah[4], al[4];
            ah[0] = *(const uint32_t*)&qh[rq * PQ + kb];
            ah[1] = *(const uint32_t*)&qh[(rq + 8) * PQ + kb];
            ah[2] = *(const uint32_t*)&qh[rq * PQ + kb + 8];
            ah[3] = *(const uint32_t*)&qh[(rq + 8) * PQ + kb + 8];
            al[0] = *(const uint32_t*)&ql[rq * PQ + kb];
            al[1] = *(const uint32_t*)&ql[(rq + 8) * PQ + kb];
            al[2] = *(const uint32_t*)&ql[rq * PQ + kb + 8];
            al[3] = *(const uint32_t*)&ql[(rq + 8) * PQ + kb + 8];
#pragma unroll
            for (int ni = 0; ni < 4; ni++) {
                int nn = wn * 32 + ni * 8 + g;
                uint32_t bh[2], bl[2];
                bh[0] = *(const uint32_t*)&kh[nn * PQ + kb];
                bh[1] = *(const uint32_t*)&kh[nn * PQ + kb + 8];
                bl[0] = *(const uint32_t*)&kl[nn * PQ + kb];
                bl[1] = *(const uint32_t*)&kl[nn * PQ + kb + 8];
                mma16816(sacc[ni], ah, bh);
                mma16816(sacc[ni], al, bh);
                mma16816(sacc[ni], ah, bl);
            }
        }
        // write scores to smem
#pragma unroll
        for (int ni = 0; ni < 4; ni++) {
            int c = wn * 32 + ni * 8 + 2 * tg;
            int row = wm * 16 + g;
            ps[row * PS + c]       = sacc[ni][0];
            ps[row * PS + c + 1]   = sacc[ni][1];
            ps[(row+8) * PS + c]   = sacc[ni][2];
            ps[(row+8) * PS + c+1] = sacc[ni][3];
        }
        __syncthreads();

        // ---- online softmax: 4 threads per row ----
        {
            const int r = tid >> 2, sg = tid & 3;
            float buf[16];
            float mloc = -1e30f;
#pragma unroll
            for (int j = 0; j < 16; j++) {
                float x = ps[r * PS + sg * 16 + j] + mk[sg * 16 + j];
                buf[j] = x;
                mloc = fmaxf(mloc, x);
            }
            mloc = fmaxf(mloc, __shfl_xor_sync(0xffffffffu, mloc, 1));
            mloc = fmaxf(mloc, __shfl_xor_sync(0xffffffffu, mloc, 2));
            float mOld = rowm[r];
            float mNew = fmaxf(mOld, mloc);
            float f = __expf(mOld - mNew);
            float ssum = 0.f;
#pragma unroll
            for (int j = 0; j < 16; j++) {
                float p = __expf(buf[j] - mNew);
                ssum += p;
                __nv_bfloat16 hp = __float2bfloat16(p);
                __nv_bfloat16 lp = __float2bfloat16(p - __bfloat162float(hp));
                ph[r * PQ + sg * 16 + j] = __bfloat16_as_ushort(hp);
                pl[r * PQ + sg * 16 + j] = __bfloat16_as_ushort(lp);
            }
            ssum += __shfl_xor_sync(0xffffffffu, ssum, 1);
            ssum += __shfl_xor_sync(0xffffffffu, ssum, 2);
            if (sg == 0) {
                rowl[r] = rowl[r] * f + ssum;
                rowm[r] = mNew;
                rowf[r] = f;
            }
        }
        __syncthreads();

        // ---- AV: ctx += P V (split bf16, 3 terms) ----
        {
            float f0 = rowf[wm * 16 + g], f1 = rowf[wm * 16 + g + 8];
#pragma unroll
            for (int ni = 0; ni < 4; ni++) {
                oacc[ni][0] *= f0; oacc[ni][1] *= f0;
                oacc[ni][2] *= f1; oacc[ni][3] *= f1;
            }
#pragma unroll
            for (int ks = 0; ks < 4; ks++) {
                const int kb = ks * 16 + 2 * tg;
                const int rq = wm * 16 + g;
                uint32_t ah[4], al[4];
                ah[0] = *(const uint32_t*)&ph[rq * PQ + kb];
                ah[1] = *(const uint32_t*)&ph[(rq + 8) * PQ + kb];
                ah[2] = *(const uint32_t*)&ph[rq * PQ + kb + 8];
                ah[3] = *(const uint32_t*)&ph[(rq + 8) * PQ + kb + 8];
                al[0] = *(const uint32_t*)&pl[rq * PQ + kb];
                al[1] = *(const uint32_t*)&pl[(rq + 8) * PQ + kb];
                al[2] = *(const uint32_t*)&pl[rq * PQ + kb + 8];
                al[3] = *(const uint32_t*)&pl[(rq + 8) * PQ + kb + 8];
#pragma unroll
                for (int ni = 0; ni < 4; ni++) {
                    int nn = wn * 32 + ni * 8 + g;   // d dimension
                    uint32_t bh[2], bl[2];
                    bh[0] = *(const uint32_t*)&vh[nn * PQ + kb];
                    bh[1] = *(const uint32_t*)&vh[nn * PQ + kb + 8];
                    bl[0] = *(const uint32_t*)&vl[nn * PQ + kb];
                    bl[1] = *(const uint32_t*)&vl[nn * PQ + kb + 8];
                    mma16816(oacc[ni], ah, bh);
                    mma16816(oacc[ni], al, bh);
                    mma16816(oacc[ni], ah, bl);
                }
            }
        }
    }

    // ---- normalize and write out (S,B,H) ----
    float inv0 = 1.f / rowl[wm * 16 + g];
    float inv1 = 1.f / rowl[wm * 16 + g + 8];
    const int b = n >> 4, h = n & 15;
#pragma unroll
    for (int ni = 0; ni < 4; ni++) {
        int d = wn * 32 + ni * 8 + 2 * tg;
        int s0 = qt * 64 + wm * 16 + g;
        float2 v0 = make_float2(oacc[ni][0] * inv0, oacc[ni][1] * inv0);
        float2 v1 = make_float2(oacc[ni][2] * inv1, oacc[ni][3] * inv1);
        *(float2*)(out + (size_t)s0 * (BATCH*HID) + b * HID + h * HDIM + d) = v0;
        *(float2*)(out + (size_t)(s0 + 8) * (BATCH*HID) + b * HID + h * HDIM + d) = v1;
    }
}

// ------------------------------------------------------------------
extern "C" void kernel_launch(void* const* d_in, const int* in_sizes, int n_in,
                              void* d_out, int out_size)
{
    const float* hs   = (const float*)d_in[0];
    const float* mask = (const float*)d_in[1];
    const float* Wq   = (const float*)d_in[2];
    const float* bq   = (const float*)d_in[3];
    const float* Wk   = (const float*)d_in[4];
    const float* bk   = (const float*)d_in[5];
    const float* Wv   = (const float*)d_in[6];
    const float* bv   = (const float*)d_in[7];
    float* out = (float*)d_out;

    unsigned short *pAhi, *pAlo, *pWhi, *pWlo;
    cudaGetSymbolAddress((void**)&pAhi, g_Ahi);
    cudaGetSymbolAddress((void**)&pAlo, g_Alo);
    cudaGetSymbolAddress((void**)&pWhi, g_Whi);
    cudaGetSymbolAddress((void**)&pWlo, g_Wlo);

    cvt_split<<<(MTOT*HID/4 + 255)/256, 256>>>(hs, pAhi, pAlo, MTOT*HID/4);
    cvt_split<<<(HID*HID/4 + 255)/256, 256>>>(Wq, pWhi,                     pWlo,                     HID*HID/4);
    cvt_split<<<(HID*HID/4 + 255)/256, 256>>>(Wk, pWhi + (size_t)HID*HID,   pWlo + (size_t)HID*HID,   HID*HID/4);
    cvt_split<<<(HID*HID/4 + 255)/256, 256>>>(Wv, pWhi + (size_t)2*HID*HID, pWlo + (size_t)2*HID*HID, HID*HID/4);

    qkv_mma<<<dim3(NTOT/128, MTOT/128), 256>>>(bq, bk, bv);

    cudaFuncSetAttribute(attn_mma, cudaFuncAttributeMaxDynamicSharedMemorySize, SMEM_ATTN);
    attn_mma<<<dim3(NH, 16), 256, SMEM_ATTN>>>(mask, out);
}

// round 4
// speedup vs baseline: 2.2596x; 1.6460x over previous
#include <cuda_runtime.h>
#include <cuda_bf16.h>
#include <cstdint>

#define S_LEN 1024
#define BATCH 4
#define HID   1024
#define NHEAD 16
#define HDIM  64
#define NH    (BATCH*NHEAD)     // 64 heads
#define MTOT  (S_LEN*BATCH)     // 4096
#define NTOT  (3*HID)           // 3072 (q|k|v stacked)

// split-bf16 GEMM operands
__device__ unsigned short g_Ahi[MTOT*HID], g_Alo[MTOT*HID];
__device__ unsigned short g_Whi[NTOT*HID], g_Wlo[NTOT*HID];
// projected tensors, split bf16.  q,k: [head][s][d]   v: [head][d][s] (transposed)
__device__ unsigned short g_qhi[NH*S_LEN*HDIM], g_qlo[NH*S_LEN*HDIM];
__device__ unsigned short g_khi[NH*S_LEN*HDIM], g_klo[NH*S_LEN*HDIM];
__device__ unsigned short g_vhi[NH*S_LEN*HDIM], g_vlo[NH*S_LEN*HDIM];

// ---------------- helpers ----------------
__device__ __forceinline__ uint32_t smem_u32(const void* p) {
    uint32_t a;
    asm("{ .reg .u64 t; cvta.to.shared.u64 t, %1; cvt.u32.u64 %0, t; }" : "=r"(a) : "l"(p));
    return a;
}
__device__ __forceinline__ void mma16816(float* c, const uint32_t* a, const uint32_t* b) {
    asm volatile("mma.sync.aligned.m16n8k16.row.col.f32.bf16.bf16.f32 "
        "{%0,%1,%2,%3},{%4,%5,%6,%7},{%8,%9},{%0,%1,%2,%3};"
        : "+f"(c[0]), "+f"(c[1]), "+f"(c[2]), "+f"(c[3])
        : "r"(a[0]), "r"(a[1]), "r"(a[2]), "r"(a[3]), "r"(b[0]), "r"(b[1]));
}
__device__ __forceinline__ void ldsm_x4(uint32_t& r0, uint32_t& r1, uint32_t& r2,
                                        uint32_t& r3, uint32_t addr) {
    asm volatile("ldmatrix.sync.aligned.m8n8.x4.shared.b16 {%0,%1,%2,%3}, [%4];"
        : "=r"(r0), "=r"(r1), "=r"(r2), "=r"(r3) : "r"(addr));
}
#define CP_ASYNC16(dst, src) \
    asm volatile("cp.async.cg.shared.global [%0], [%1], 16;" :: "r"(dst), "l"(src))
#define CP_COMMIT asm volatile("cp.async.commit_group;" ::: "memory")
#define CP_WAIT0  asm volatile("cp.async.wait_group 0;" ::: "memory")

__device__ __forceinline__ void split2(float x, float y, uint32_t& hi, uint32_t& lo) {
    __nv_bfloat16 hx = __float2bfloat16(x);
    __nv_bfloat16 hy = __float2bfloat16(y);
    __nv_bfloat16 lx = __float2bfloat16(x - __bfloat162float(hx));
    __nv_bfloat16 ly = __float2bfloat16(y - __bfloat162float(hy));
    hi = (uint32_t)__bfloat16_as_ushort(hx) | ((uint32_t)__bfloat16_as_ushort(hy) << 16);
    lo = (uint32_t)__bfloat16_as_ushort(lx) | ((uint32_t)__bfloat16_as_ushort(ly) << 16);
}

// ---------------- split-bf16 conversion ----------------
__global__ __launch_bounds__(256)
void cvt_split(const float* __restrict__ src, unsigned short* __restrict__ hi,
               unsigned short* __restrict__ lo, int n4)
{
    int i = blockIdx.x * blockDim.x + threadIdx.x;
    if (i >= n4) return;
    float4 x = ((const float4*)src)[i];
    ushort4 h, l;
    __nv_bfloat16 b;
    b = __float2bfloat16(x.x); h.x = __bfloat16_as_ushort(b);
    l.x = __bfloat16_as_ushort(__float2bfloat16(x.x - __bfloat162float(b)));
    b = __float2bfloat16(x.y); h.y = __bfloat16_as_ushort(b);
    l.y = __bfloat16_as_ushort(__float2bfloat16(x.y - __bfloat162float(b)));
    b = __float2bfloat16(x.z); h.z = __bfloat16_as_ushort(b);
    l.z = __bfloat16_as_ushort(__float2bfloat16(x.z - __bfloat162float(b)));
    b = __float2bfloat16(x.w); h.w = __bfloat16_as_ushort(b);
    l.w = __bfloat16_as_ushort(__float2bfloat16(x.w - __bfloat162float(b)));
    ((ushort4*)hi)[i] = h;
    ((ushort4*)lo)[i] = l;
}

// ================= QKV GEMM: cp.async + ldmatrix + double buffer =================
// C[4096 x 3072] = A @ W^T (+bias). Tile 128x128, BK=32, 8 warps m64n32.
#define GST 40                       // smem row stride (ushorts), conflict-free
#define QKV_STAGE (4*128*GST)        // ushorts per stage (Ah|Al|Wh|Wl)
#define QKV_SMEM  (2*QKV_STAGE*2)    // bytes

__global__ __launch_bounds__(256)
void qkv_mma(const float* __restrict__ bq, const float* __restrict__ bk,
             const float* __restrict__ bv)
{
    extern __shared__ unsigned short smq[];
    const int tid = threadIdx.x, lane = tid & 31, wid = tid >> 5;
    const int wm = wid >> 2, wn = wid & 3;
    const int g = lane >> 2, tg = lane & 3;
    const int m0 = blockIdx.y * 128, c0 = blockIdx.x * 128;
    const uint32_t sbase = smem_u32(smq);

    float acc[4][4][4];
#pragma unroll
    for (int i = 0; i < 4; i++)
#pragma unroll
        for (int j = 0; j < 4; j++)
#pragma unroll
            for (int k = 0; k < 4; k++) acc[i][j][k] = 0.f;

    // loader: thread pair per row, 2 x 16B each per matrix
    const int lrow = tid >> 1, lhalf = tid & 1;
    const unsigned short* gA0 = g_Ahi + (size_t)(m0 + lrow) * HID + lhalf * 16;
    const unsigned short* gA1 = g_Alo + (size_t)(m0 + lrow) * HID + lhalf * 16;
    const unsigned short* gW0 = g_Whi + (size_t)(c0 + lrow) * HID + lhalf * 16;
    const unsigned short* gW1 = g_Wlo + (size_t)(c0 + lrow) * HID + lhalf * 16;
    const uint32_t dOff = (uint32_t)(lrow * GST + lhalf * 16) * 2;

    // ldmatrix address pieces
    const int aRow = wm * 64 + (lane & 15);
    const int aK   = (lane >> 4) * 8;
    const int bRow = wn * 32 + (lane & 7) + ((lane >> 4) << 3);
    const int bK   = ((lane >> 3) & 1) * 8;

#define QKV_ISSUE(CH, STG) do { \
    int k0 = (CH) * 32; \
    uint32_t dst = sbase + (uint32_t)(STG) * QKV_STAGE * 2 + dOff; \
    CP_ASYNC16(dst,                       gA0 + k0); \
    CP_ASYNC16(dst + 16,                  gA0 + k0 + 8); \
    CP_ASYNC16(dst + 128*GST*2,           gA1 + k0); \
    CP_ASYNC16(dst + 128*GST*2 + 16,      gA1 + k0 + 8); \
    CP_ASYNC16(dst + 2*128*GST*2,         gW0 + k0); \
    CP_ASYNC16(dst + 2*128*GST*2 + 16,    gW0 + k0 + 8); \
    CP_ASYNC16(dst + 3*128*GST*2,         gW1 + k0); \
    CP_ASYNC16(dst + 3*128*GST*2 + 16,    gW1 + k0 + 8); \
    CP_COMMIT; } while (0)

    QKV_ISSUE(0, 0);

    for (int ch = 0; ch < 32; ch++) {
        const int stg = ch & 1;
        CP_WAIT0;
        __syncthreads();
        if (ch < 31) QKV_ISSUE(ch + 1, stg ^ 1);

        const uint32_t base = sbase + (uint32_t)stg * QKV_STAGE * 2;
#pragma unroll
        for (int ks = 0; ks < 2; ks++) {
            uint32_t ah[4][4], al[4][4];
#pragma unroll
            for (int mi = 0; mi < 4; mi++) {
                uint32_t ra = base + (uint32_t)((aRow + mi*16) * GST + ks*16 + aK) * 2;
                ldsm_x4(ah[mi][0], ah[mi][1], ah[mi][2], ah[mi][3], ra);
                ldsm_x4(al[mi][0], al[mi][1], al[mi][2], al[mi][3], ra + 128*GST*2);
            }
#pragma unroll
            for (int np = 0; np < 2; np++) {
                uint32_t bh[4], bl[4];
                uint32_t rb = base + (uint32_t)(2*128*GST + (bRow + np*16) * GST + ks*16 + bK) * 2;
                ldsm_x4(bh[0], bh[1], bh[2], bh[3], rb);
                ldsm_x4(bl[0], bl[1], bl[2], bl[3], rb + 128*GST*2);
#pragma unroll
                for (int j = 0; j < 2; j++) {
                    const int ni = np * 2 + j;
#pragma unroll
                    for (int mi = 0; mi < 4; mi++) {
                        mma16816(acc[mi][ni], ah[mi], &bh[2*j]);
                        mma16816(acc[mi][ni], al[mi], &bh[2*j]);
                        mma16816(acc[mi][ni], ah[mi], &bl[2*j]);
                    }
                }
            }
        }
        __syncthreads();
    }

    // epilogue: bias (+0.125 folded into Q), split-bf16, scatter
    const int which = c0 >> 10;
    const float* bias = (which == 0) ? bq : ((which == 1) ? bk : bv);
    const float qsc = (which == 0) ? 0.125f : 1.0f;

#pragma unroll
    for (int mi = 0; mi < 4; mi++) {
#pragma unroll
        for (int ni = 0; ni < 4; ni++) {
            int colE = c0 + wn * 32 + ni * 8 + 2 * tg;
            int bcol = colE & 1023;
            float b0f = bias[bcol], b1f = bias[bcol + 1];
            int hh = (colE >> 6) & 15, dd = colE & 63;
#pragma unroll
            for (int hr = 0; hr < 2; hr++) {
                int row = m0 + wm * 64 + mi * 16 + g + hr * 8;
                int s = row >> 2, b = row & 3;
                float x = (acc[mi][ni][hr * 2 + 0] + b0f) * qsc;
                float y = (acc[mi][ni][hr * 2 + 1] + b1f) * qsc;
                uint32_t hi, lo;
                split2(x, y, hi, lo);
                int head = b * NHEAD + hh;
                if (which == 0) {
                    size_t idx = ((size_t)head * S_LEN + s) * HDIM + dd;
                    *(uint32_t*)&g_qhi[idx] = hi;
                    *(uint32_t*)&g_qlo[idx] = lo;
                } else if (which == 1) {
                    size_t idx = ((size_t)head * S_LEN + s) * HDIM + dd;
                    *(uint32_t*)&g_khi[idx] = hi;
                    *(uint32_t*)&g_klo[idx] = lo;
                } else {
                    size_t idx = ((size_t)head * HDIM + dd) * S_LEN + s;
                    g_vhi[idx]         = (unsigned short)(hi & 0xffff);
                    g_vhi[idx + S_LEN] = (unsigned short)(hi >> 16);
                    g_vlo[idx]         = (unsigned short)(lo & 0xffff);
                    g_vlo[idx + S_LEN] = (unsigned short)(lo >> 16);
                }
            }
        }
    }
}

// ================= register-resident flash attention =================
// block = (head, 128-query tile); 8 warps, warp w owns rows w*16..w*16+15.
// Softmax fully in registers; P fragments fed back into AV MMA directly.
#define KST 72                      // KV smem row stride (ushorts)
#define ATT_STAGE (4*64*KST)        // ushorts per stage (Kh|Kl|Vh|Vl)
#define ATT_SMEM (2*ATT_STAGE*2 + S_LEN*4)

__global__ __launch_bounds__(256)
void attn_mma(const float* __restrict__ mask, float* __restrict__ out)
{
    extern __shared__ unsigned short sma[];
    float* msm = (float*)(sma + 2 * ATT_STAGE);     // [1024] mask row
    const int n = blockIdx.x, qt = blockIdx.y;
    const int tid = threadIdx.x, lane = tid & 31, wid = tid >> 5;
    const int g = lane >> 2, tg = lane & 3;
    const uint32_t sbase = smem_u32(sma);

    // preload the full mask row for this head
    *(float4*)&msm[tid * 4] = *(const float4*)(mask + (size_t)n * S_LEN + tid * 4);

    // Q fragments in registers (Q already holds the 1/8 scale)
    uint32_t aqh[4][4], aql[4][4];
    {
        const int row = qt * 128 + wid * 16 + g;
        const unsigned short* qh = g_qhi + ((size_t)n * S_LEN + row) * HDIM;
        const unsigned short* ql = g_qlo + ((size_t)n * S_LEN + row) * HDIM;
#pragma unroll
        for (int ks = 0; ks < 4; ks++) {
            int k = ks * 16 + 2 * tg;
            aqh[ks][0] = *(const uint32_t*)(qh + k);
            aqh[ks][1] = *(const uint32_t*)(qh + 8*HDIM + k);
            aqh[ks][2] = *(const uint32_t*)(qh + k + 8);
            aqh[ks][3] = *(const uint32_t*)(qh + 8*HDIM + k + 8);
            aql[ks][0] = *(const uint32_t*)(ql + k);
            aql[ks][1] = *(const uint32_t*)(ql + 8*HDIM + k);
            aql[ks][2] = *(const uint32_t*)(ql + k + 8);
            aql[ks][3] = *(const uint32_t*)(ql + 8*HDIM + k + 8);
        }
    }

    float oacc[8][4];
#pragma unroll
    for (int i = 0; i < 8; i++)
#pragma unroll
        for (int j = 0; j < 4; j++) oacc[i][j] = 0.f;
    float m0 = -1e30f, m1 = -1e30f, l0 = 0.f, l1 = 0.f;

    // loaders
    const int lrow = tid >> 2, lseg = (tid & 3) * 2;
    const unsigned short* gkh = g_khi + (size_t)n * S_LEN * HDIM;
    const unsigned short* gkl = g_klo + (size_t)n * S_LEN * HDIM;
    const unsigned short* gvh = g_vhi + (size_t)n * S_LEN * HDIM + (size_t)lrow * S_LEN;
    const unsigned short* gvl = g_vlo + (size_t)n * S_LEN * HDIM + (size_t)lrow * S_LEN;
    const uint32_t dKV = (uint32_t)(lrow * KST + lseg * 8) * 2;

#define ATT_ISSUE(KT, STG) do { \
    uint32_t dst = sbase + (uint32_t)(STG) * ATT_STAGE * 2 + dKV; \
    const unsigned short* sk = gkh + ((KT)*64 + lrow) * HDIM + lseg * 8; \
    const unsigned short* sl = gkl + ((KT)*64 + lrow) * HDIM + lseg * 8; \
    const unsigned short* sv = gvh + (KT)*64 + lseg * 8; \
    const unsigned short* sw = gvl + (KT)*64 + lseg * 8; \
    CP_ASYNC16(dst,                    sk);      CP_ASYNC16(dst + 16,                    sk + 8); \
    CP_ASYNC16(dst + 64*KST*2,         sl);      CP_ASYNC16(dst + 64*KST*2 + 16,         sl + 8); \
    CP_ASYNC16(dst + 2*64*KST*2,       sv);      CP_ASYNC16(dst + 2*64*KST*2 + 16,       sv + 8); \
    CP_ASYNC16(dst + 3*64*KST*2,       sw);      CP_ASYNC16(dst + 3*64*KST*2 + 16,       sw + 8); \
    CP_COMMIT; } while (0)

    const int bRow = (lane & 7) + ((lane >> 4) << 3);
    const int bK   = ((lane >> 3) & 1) * 8;

    ATT_ISSUE(0, 0);

    for (int kt = 0; kt < 16; kt++) {
        const int stg = kt & 1;
        CP_WAIT0;
        __syncthreads();
        if (kt < 15) ATT_ISSUE(kt + 1, stg ^ 1);

        const uint32_t base = sbase + (uint32_t)stg * ATT_STAGE * 2;

        // ---- QK^T: sacc[ni][4] over 64 keys ----
        float sacc[8][4];
#pragma unroll
        for (int i = 0; i < 8; i++)
#pragma unroll
            for (int j = 0; j < 4; j++) sacc[i][j] = 0.f;

#pragma unroll
        for (int ks = 0; ks < 4; ks++) {
#pragma unroll
            for (int np = 0; np < 4; np++) {
                uint32_t bh[4], bl[4];
                uint32_t rb = base + (uint32_t)((np*16 + bRow) * KST + ks*16 + bK) * 2;
                ldsm_x4(bh[0], bh[1], bh[2], bh[3], rb);
                ldsm_x4(bl[0], bl[1], bl[2], bl[3], rb + 64*KST*2);
#pragma unroll
                for (int j = 0; j < 2; j++) {
                    const int ni = np * 2 + j;
                    mma16816(sacc[ni], aqh[ks], &bh[2*j]);
                    mma16816(sacc[ni], aql[ks], &bh[2*j]);
                    mma16816(sacc[ni], aqh[ks], &bl[2*j]);
                }
            }
        }

        // ---- register softmax (quad-reduced) ----
        float mx0 = -1e30f, mx1 = -1e30f;
#pragma unroll
        for (int ni = 0; ni < 8; ni++) {
            float2 mk = *(const float2*)&msm[kt*64 + ni*8 + 2*tg];
            sacc[ni][0] += mk.x; sacc[ni][1] += mk.y;
            sacc[ni][2] += mk.x; sacc[ni][3] += mk.y;
            mx0 = fmaxf(mx0, fmaxf(sacc[ni][0], sacc[ni][1]));
            mx1 = fmaxf(mx1, fmaxf(sacc[ni][2], sacc[ni][3]));
        }
        mx0 = fmaxf(mx0, __shfl_xor_sync(0xffffffffu, mx0, 1));
        mx0 = fmaxf(mx0, __shfl_xor_sync(0xffffffffu, mx0, 2));
        mx1 = fmaxf(mx1, __shfl_xor_sync(0xffffffffu, mx1, 1));
        mx1 = fmaxf(mx1, __shfl_xor_sync(0xffffffffu, mx1, 2));
        float m0n = fmaxf(m0, mx0), m1n = fmaxf(m1, mx1);
        float f0 = __expf(m0 - m0n), f1 = __expf(m1 - m1n);
        m0 = m0n; m1 = m1n;
        float s0 = 0.f, s1 = 0.f;
#pragma unroll
        for (int ni = 0; ni < 8; ni++) {
            sacc[ni][0] = __expf(sacc[ni][0] - m0n);
            sacc[ni][1] = __expf(sacc[ni][1] - m0n);
            sacc[ni][2] = __expf(sacc[ni][2] - m1n);
            sacc[ni][3] = __expf(sacc[ni][3] - m1n);
            s0 += sacc[ni][0] + sacc[ni][1];
            s1 += sacc[ni][2] + sacc[ni][3];
        }
        s0 += __shfl_xor_sync(0xffffffffu, s0, 1);
        s0 += __shfl_xor_sync(0xffffffffu, s0, 2);
        s1 += __shfl_xor_sync(0xffffffffu, s1, 1);
        s1 += __shfl_xor_sync(0xffffffffu, s1, 2);
        l0 = l0 * f0 + s0;
        l1 = l1 * f1 + s1;
#pragma unroll
        for (int ni = 0; ni < 8; ni++) {
            oacc[ni][0] *= f0; oacc[ni][1] *= f0;
            oacc[ni][2] *= f1; oacc[ni][3] *= f1;
        }

        // ---- AV: P fragments straight from registers ----
#pragma unroll
        for (int kk = 0; kk < 4; kk++) {
            uint32_t pah[4], pal[4];
            split2(sacc[2*kk][0],   sacc[2*kk][1],   pah[0], pal[0]);
            split2(sacc[2*kk][2],   sacc[2*kk][3],   pah[1], pal[1]);
            split2(sacc[2*kk+1][0], sacc[2*kk+1][1], pah[2], pal[2]);
            split2(sacc[2*kk+1][2], sacc[2*kk+1][3], pah[3], pal[3]);
#pragma unroll
            for (int np = 0; np < 4; np++) {
                uint32_t vh[4], vl[4];
                uint32_t rb = base + (uint32_t)(2*64*KST + (np*16 + bRow) * KST + kk*16 + bK) * 2;
                ldsm_x4(vh[0], vh[1], vh[2], vh[3], rb);
                ldsm_x4(vl[0], vl[1], vl[2], vl[3], rb + 64*KST*2);
#pragma unroll
                for (int j = 0; j < 2; j++) {
                    const int ni = np * 2 + j;
                    mma16816(oacc[ni], pah, &vh[2*j]);
                    mma16816(oacc[ni], pal, &vh[2*j]);
                    mma16816(oacc[ni], pah, &vl[2*j]);
                }
            }
        }
        __syncthreads();
    }

    // ---- normalize, write (S,B,H) ----
    const float inv0 = 1.f / l0, inv1 = 1.f / l1;
    const int b = n >> 4, h = n & 15;
    const int row0 = qt * 128 + wid * 16 + g;
#pragma unroll
    for (int ni = 0; ni < 8; ni++) {
        int d = ni * 8 + 2 * tg;
        float2 v0 = make_float2(oacc[ni][0] * inv0, oacc[ni][1] * inv0);
        float2 v1 = make_float2(oacc[ni][2] * inv1, oacc[ni][3] * inv1);
        *(float2*)(out + (size_t)row0 * (BATCH*HID) + b * HID + h * HDIM + d) = v0;
        *(float2*)(out + (size_t)(row0 + 8) * (BATCH*HID) + b * HID + h * HDIM + d) = v1;
    }
}

// ------------------------------------------------------------------
extern "C" void kernel_launch(void* const* d_in, const int* in_sizes, int n_in,
                              void* d_out, int out_size)
{
    const float* hs   = (const float*)d_in[0];
    const float* mask = (const float*)d_in[1];
    const float* Wq   = (const float*)d_in[2];
    const float* bq   = (const float*)d_in[3];
    const float* Wk   = (const float*)d_in[4];
    const float* bk   = (const float*)d_in[5];
    const float* Wv   = (const float*)d_in[6];
    const float* bv   = (const float*)d_in[7];
    float* out = (float*)d_out;

    unsigned short *pAhi, *pAlo, *pWhi, *pWlo;
    cudaGetSymbolAddress((void**)&pAhi, g_Ahi);
    cudaGetSymbolAddress((void**)&pAlo, g_Alo);
    cudaGetSymbolAddress((void**)&pWhi, g_Whi);
    cudaGetSymbolAddress((void**)&pWlo, g_Wlo);

    cvt_split<<<(MTOT*HID/4 + 255)/256, 256>>>(hs, pAhi, pAlo, MTOT*HID/4);
    cvt_split<<<(HID*HID/4 + 255)/256, 256>>>(Wq, pWhi,                     pWlo,                     HID*HID/4);
    cvt_split<<<(HID*HID/4 + 255)/256, 256>>>(Wk, pWhi + (size_t)HID*HID,   pWlo + (size_t)HID*HID,   HID*HID/4);
    cvt_split<<<(HID*HID/4 + 255)/256, 256>>>(Wv, pWhi + (size_t)2*HID*HID, pWlo + (size_t)2*HID*HID, HID*HID/4);

    cudaFuncSetAttribute(qkv_mma, cudaFuncAttributeMaxDynamicSharedMemorySize, QKV_SMEM);
    qkv_mma<<<dim3(NTOT/128, MTOT/128), 256, QKV_SMEM>>>(bq, bk, bv);

    cudaFuncSetAttribute(attn_mma, cudaFuncAttributeMaxDynamicSharedMemorySize, ATT_SMEM);
    attn_mma<<<dim3(NH, S_LEN/128), 256, ATT_SMEM>>>(mask, out);
}

// round 5
// speedup vs baseline: 2.3427x; 1.0368x over previous
#include <cuda_runtime.h>
#include <cuda_bf16.h>
#include <cstdint>

#define S_LEN 1024
#define BATCH 4
#define HID   1024
#define NHEAD 16
#define HDIM  64
#define NH    (BATCH*NHEAD)     // 64 heads
#define MTOT  (S_LEN*BATCH)     // 4096
#define NTOT  (3*HID)           // 3072 (q|k|v stacked)

// split-bf16 GEMM operands
__device__ unsigned short g_Ahi[MTOT*HID], g_Alo[MTOT*HID];
__device__ unsigned short g_Whi[NTOT*HID], g_Wlo[NTOT*HID];
// projected tensors, split bf16.  q,k: [head][s][d]   v: [head][d][s] (transposed)
__device__ unsigned short g_qhi[NH*S_LEN*HDIM], g_qlo[NH*S_LEN*HDIM];
__device__ unsigned short g_khi[NH*S_LEN*HDIM], g_klo[NH*S_LEN*HDIM];
__device__ unsigned short g_vhi[NH*S_LEN*HDIM], g_vlo[NH*S_LEN*HDIM];

// ---------------- helpers ----------------
__device__ __forceinline__ uint32_t smem_u32(const void* p) {
    uint32_t a;
    asm("{ .reg .u64 t; cvta.to.shared.u64 t, %1; cvt.u32.u64 %0, t; }" : "=r"(a) : "l"(p));
    return a;
}
__device__ __forceinline__ void mma16816(float* c, const uint32_t* a, const uint32_t* b) {
    asm volatile("mma.sync.aligned.m16n8k16.row.col.f32.bf16.bf16.f32 "
        "{%0,%1,%2,%3},{%4,%5,%6,%7},{%8,%9},{%0,%1,%2,%3};"
        : "+f"(c[0]), "+f"(c[1]), "+f"(c[2]), "+f"(c[3])
        : "r"(a[0]), "r"(a[1]), "r"(a[2]), "r"(a[3]), "r"(b[0]), "r"(b[1]));
}
__device__ __forceinline__ void ldsm_x4(uint32_t& r0, uint32_t& r1, uint32_t& r2,
                                        uint32_t& r3, uint32_t addr) {
    asm volatile("ldmatrix.sync.aligned.m8n8.x4.shared.b16 {%0,%1,%2,%3}, [%4];"
        : "=r"(r0), "=r"(r1), "=r"(r2), "=r"(r3) : "r"(addr));
}
#define CP_ASYNC16(dst, src) \
    asm volatile("cp.async.cg.shared.global [%0], [%1], 16;" :: "r"(dst), "l"(src))
#define CP_COMMIT asm volatile("cp.async.commit_group;" ::: "memory")
#define CP_WAIT0  asm volatile("cp.async.wait_group 0;" ::: "memory")

__device__ __forceinline__ void split2(float x, float y, uint32_t& hi, uint32_t& lo) {
    __nv_bfloat16 hx = __float2bfloat16(x);
    __nv_bfloat16 hy = __float2bfloat16(y);
    __nv_bfloat16 lx = __float2bfloat16(x - __bfloat162float(hx));
    __nv_bfloat16 ly = __float2bfloat16(y - __bfloat162float(hy));
    hi = (uint32_t)__bfloat16_as_ushort(hx) | ((uint32_t)__bfloat16_as_ushort(hy) << 16);
    lo = (uint32_t)__bfloat16_as_ushort(lx) | ((uint32_t)__bfloat16_as_ushort(ly) << 16);
}

// ---------------- fused split-bf16 conversion (one launch) ----------------
// blocks [0,4096): hidden -> g_Ahi/g_Alo ; [4096,7168): Wq|Wk|Wv -> g_Whi/g_Wlo
__global__ __launch_bounds__(256)
void cvt_all(const float* __restrict__ hs, const float* __restrict__ Wq,
             const float* __restrict__ Wk, const float* __restrict__ Wv)
{
    const int bid = blockIdx.x;
    const float* src;
    unsigned short *hi, *lo;
    size_t off;
    if (bid < 4096) {
        src = hs; hi = g_Ahi; lo = g_Alo;
        off = (size_t)bid * 1024 + threadIdx.x * 4;
    } else {
        int w  = (bid - 4096) >> 10;
        int lb = (bid - 4096) & 1023;
        src = (w == 0) ? Wq : ((w == 1) ? Wk : Wv);
        hi = g_Whi + (size_t)w * HID * HID;
        lo = g_Wlo + (size_t)w * HID * HID;
        off = (size_t)lb * 1024 + threadIdx.x * 4;
    }
    float4 x = *(const float4*)(src + off);
    ushort4 h, l;
    __nv_bfloat16 b;
    b = __float2bfloat16(x.x); h.x = __bfloat16_as_ushort(b);
    l.x = __bfloat16_as_ushort(__float2bfloat16(x.x - __bfloat162float(b)));
    b = __float2bfloat16(x.y); h.y = __bfloat16_as_ushort(b);
    l.y = __bfloat16_as_ushort(__float2bfloat16(x.y - __bfloat162float(b)));
    b = __float2bfloat16(x.z); h.z = __bfloat16_as_ushort(b);
    l.z = __bfloat16_as_ushort(__float2bfloat16(x.z - __bfloat162float(b)));
    b = __float2bfloat16(x.w); h.w = __bfloat16_as_ushort(b);
    l.w = __bfloat16_as_ushort(__float2bfloat16(x.w - __bfloat162float(b)));
    *(ushort4*)(hi + off) = h;
    *(ushort4*)(lo + off) = l;
}

// ================= QKV GEMM: cp.async + ldmatrix + double buffer =================
#define GST 40                       // smem row stride (ushorts), conflict-free
#define QKV_STAGE (4*128*GST)        // ushorts per stage (Ah|Al|Wh|Wl)
#define QKV_SMEM  (2*QKV_STAGE*2)    // bytes (81920)
#define MST 130                      // V-transpose tile stride (ushorts)

__global__ __launch_bounds__(256)
void qkv_mma(const float* __restrict__ bq, const float* __restrict__ bk,
             const float* __restrict__ bv)
{
    extern __shared__ unsigned short smq[];
    const int tid = threadIdx.x, lane = tid & 31, wid = tid >> 5;
    const int wm = wid >> 2, wn = wid & 3;
    const int g = lane >> 2, tg = lane & 3;
    const int m0 = blockIdx.y * 128, c0 = blockIdx.x * 128;
    const uint32_t sbase = smem_u32(smq);

    float acc[4][4][4];
#pragma unroll
    for (int i = 0; i < 4; i++)
#pragma unroll
        for (int j = 0; j < 4; j++)
#pragma unroll
            for (int k = 0; k < 4; k++) acc[i][j][k] = 0.f;

    const int lrow = tid >> 1, lhalf = tid & 1;
    const unsigned short* gA0 = g_Ahi + (size_t)(m0 + lrow) * HID + lhalf * 16;
    const unsigned short* gA1 = g_Alo + (size_t)(m0 + lrow) * HID + lhalf * 16;
    const unsigned short* gW0 = g_Whi + (size_t)(c0 + lrow) * HID + lhalf * 16;
    const unsigned short* gW1 = g_Wlo + (size_t)(c0 + lrow) * HID + lhalf * 16;
    const uint32_t dOff = (uint32_t)(lrow * GST + lhalf * 16) * 2;

    const int aRow = wm * 64 + (lane & 15);
    const int aK   = (lane >> 4) * 8;
    const int bRow = wn * 32 + (lane & 7) + ((lane >> 4) << 3);
    const int bK   = ((lane >> 3) & 1) * 8;

#define QKV_ISSUE(CH, STG) do { \
    int k0 = (CH) * 32; \
    uint32_t dst = sbase + (uint32_t)(STG) * QKV_STAGE * 2 + dOff; \
    CP_ASYNC16(dst,                       gA0 + k0); \
    CP_ASYNC16(dst + 16,                  gA0 + k0 + 8); \
    CP_ASYNC16(dst + 128*GST*2,           gA1 + k0); \
    CP_ASYNC16(dst + 128*GST*2 + 16,      gA1 + k0 + 8); \
    CP_ASYNC16(dst + 2*128*GST*2,         gW0 + k0); \
    CP_ASYNC16(dst + 2*128*GST*2 + 16,    gW0 + k0 + 8); \
    CP_ASYNC16(dst + 3*128*GST*2,         gW1 + k0); \
    CP_ASYNC16(dst + 3*128*GST*2 + 16,    gW1 + k0 + 8); \
    CP_COMMIT; } while (0)

    QKV_ISSUE(0, 0);

    for (int ch = 0; ch < 32; ch++) {
        const int stg = ch & 1;
        CP_WAIT0;
        __syncthreads();            // single barrier per stage (see R5 analysis)
        if (ch < 31) QKV_ISSUE(ch + 1, stg ^ 1);

        const uint32_t base = sbase + (uint32_t)stg * QKV_STAGE * 2;
#pragma unroll
        for (int ks = 0; ks < 2; ks++) {
            uint32_t ah[4][4], al[4][4];
#pragma unroll
            for (int mi = 0; mi < 4; mi++) {
                uint32_t ra = base + (uint32_t)((aRow + mi*16) * GST + ks*16 + aK) * 2;
                ldsm_x4(ah[mi][0], ah[mi][1], ah[mi][2], ah[mi][3], ra);
                ldsm_x4(al[mi][0], al[mi][1], al[mi][2], al[mi][3], ra + 128*GST*2);
            }
#pragma unroll
            for (int np = 0; np < 2; np++) {
                uint32_t bh[4], bl[4];
                uint32_t rb = base + (uint32_t)(2*128*GST + (bRow + np*16) * GST + ks*16 + bK) * 2;
                ldsm_x4(bh[0], bh[1], bh[2], bh[3], rb);
                ldsm_x4(bl[0], bl[1], bl[2], bl[3], rb + 128*GST*2);
#pragma unroll
                for (int j = 0; j < 2; j++) {
                    const int ni = np * 2 + j;
#pragma unroll
                    for (int mi = 0; mi < 4; mi++) {
                        mma16816(acc[mi][ni], ah[mi], &bh[2*j]);
                        mma16816(acc[mi][ni], al[mi], &bh[2*j]);
                        mma16816(acc[mi][ni], ah[mi], &bl[2*j]);
                    }
                }
            }
        }
    }

    const int which = c0 >> 10;
    const float* bias = (which == 0) ? bq : ((which == 1) ? bk : bv);
    const float qsc = (which == 0) ? 0.125f : 1.0f;

    if (which < 2) {
        // Q / K: direct coalesced-ish scatter (16B per quad)
#pragma unroll
        for (int mi = 0; mi < 4; mi++) {
#pragma unroll
            for (int ni = 0; ni < 4; ni++) {
                int colE = c0 + wn * 32 + ni * 8 + 2 * tg;
                int bcol = colE & 1023;
                float b0f = bias[bcol], b1f = bias[bcol + 1];
                int hh = (colE >> 6) & 15, dd = colE & 63;
#pragma unroll
                for (int hr = 0; hr < 2; hr++) {
                    int row = m0 + wm * 64 + mi * 16 + g + hr * 8;
                    int s = row >> 2, b = row & 3;
                    float x = (acc[mi][ni][hr * 2 + 0] + b0f) * qsc;
                    float y = (acc[mi][ni][hr * 2 + 1] + b1f) * qsc;
                    uint32_t hi, lo;
                    split2(x, y, hi, lo);
                    size_t idx = ((size_t)((b * NHEAD + hh)) * S_LEN + s) * HDIM + dd;
                    if (which == 0) {
                        *(uint32_t*)&g_qhi[idx] = hi;
                        *(uint32_t*)&g_qlo[idx] = lo;
                    } else {
                        *(uint32_t*)&g_khi[idx] = hi;
                        *(uint32_t*)&g_klo[idx] = lo;
                    }
                }
            }
        }
    } else {
        // V: transpose through smem, then coalesced [head][d][s] writes
        unsigned short* Th = smq;
        unsigned short* Tl = smq + 128 * MST;
        __syncthreads();            // all stage reads done before tile reuse
#pragma unroll
        for (int mi = 0; mi < 4; mi++) {
#pragma unroll
            for (int ni = 0; ni < 4; ni++) {
                int col = wn * 32 + ni * 8 + 2 * tg;
                int bcol = (c0 + col) & 1023;
                float b0f = bias[bcol], b1f = bias[bcol + 1];
#pragma unroll
                for (int hr = 0; hr < 2; hr++) {
                    int rloc = wm * 64 + mi * 16 + g + hr * 8;
                    float x = acc[mi][ni][hr * 2 + 0] + b0f;
                    float y = acc[mi][ni][hr * 2 + 1] + b1f;
                    uint32_t hi, lo;
                    split2(x, y, hi, lo);
                    Th[col * MST + rloc]       = (unsigned short)(hi & 0xffff);
                    Th[(col + 1) * MST + rloc] = (unsigned short)(hi >> 16);
                    Tl[col * MST + rloc]       = (unsigned short)(lo & 0xffff);
                    Tl[(col + 1) * MST + rloc] = (unsigned short)(lo >> 16);
                }
            }
        }
        __syncthreads();
        // 512 slices (col,b); each = 32 consecutive s -> 64B contiguous store
#pragma unroll
        for (int rep = 0; rep < 2; rep++) {
            int sid = tid + rep * 256;
            int col = sid >> 2, b = sid & 3;
            int cg = c0 + col;
            int hh = (cg >> 6) & 15, dd = cg & 63;
            size_t gb = ((size_t)(b * NHEAD + hh) * HDIM + dd) * S_LEN + (m0 >> 2);
            uint32_t uh[16], ul[16];
#pragma unroll
            for (int j = 0; j < 16; j++) {
                uh[j] = (uint32_t)Th[col * MST + (2*j) * 4 + b]
                      | ((uint32_t)Th[col * MST + (2*j + 1) * 4 + b] << 16);
                ul[j] = (uint32_t)Tl[col * MST + (2*j) * 4 + b]
                      | ((uint32_t)Tl[col * MST + (2*j + 1) * 4 + b] << 16);
            }
#pragma unroll
            for (int j = 0; j < 4; j++) {
                *(uint4*)(g_vhi + gb + j * 8) = make_uint4(uh[4*j], uh[4*j+1], uh[4*j+2], uh[4*j+3]);
                *(uint4*)(g_vlo + gb + j * 8) = make_uint4(ul[4*j], ul[4*j+1], ul[4*j+2], ul[4*j+3]);
            }
        }
    }
}

// ================= register-resident flash attention =================
#define KST 72
#define ATT_STAGE (4*64*KST)
#define ATT_SMEM (2*ATT_STAGE*2 + S_LEN*4)

__global__ __launch_bounds__(256)
void attn_mma(const float* __restrict__ mask, float* __restrict__ out)
{
    extern __shared__ unsigned short sma[];
    float* msm = (float*)(sma + 2 * ATT_STAGE);
    const int n = blockIdx.x, qt = blockIdx.y;
    const int tid = threadIdx.x, lane = tid & 31, wid = tid >> 5;
    const int g = lane >> 2, tg = lane & 3;
    const uint32_t sbase = smem_u32(sma);

    *(float4*)&msm[tid * 4] = *(const float4*)(mask + (size_t)n * S_LEN + tid * 4);

    uint32_t aqh[4][4], aql[4][4];
    {
        const int row = qt * 128 + wid * 16 + g;
        const unsigned short* qh = g_qhi + ((size_t)n * S_LEN + row) * HDIM;
        const unsigned short* ql = g_qlo + ((size_t)n * S_LEN + row) * HDIM;
#pragma unroll
        for (int ks = 0; ks < 4; ks++) {
            int k = ks * 16 + 2 * tg;
            aqh[ks][0] = *(const uint32_t*)(qh + k);
            aqh[ks][1] = *(const uint32_t*)(qh + 8*HDIM + k);
            aqh[ks][2] = *(const uint32_t*)(qh + k + 8);
            aqh[ks][3] = *(const uint32_t*)(qh + 8*HDIM + k + 8);
            aql[ks][0] = *(const uint32_t*)(ql + k);
            aql[ks][1] = *(const uint32_t*)(ql + 8*HDIM + k);
            aql[ks][2] = *(const uint32_t*)(ql + k + 8);
            aql[ks][3] = *(const uint32_t*)(ql + 8*HDIM + k + 8);
        }
    }

    float oacc[8][4];
#pragma unroll
    for (int i = 0; i < 8; i++)
#pragma unroll
        for (int j = 0; j < 4; j++) oacc[i][j] = 0.f;
    float m0 = -1e30f, m1 = -1e30f, l0 = 0.f, l1 = 0.f;

    const int lrow = tid >> 2, lseg = (tid & 3) * 2;
    const unsigned short* gkh = g_khi + (size_t)n * S_LEN * HDIM;
    const unsigned short* gkl = g_klo + (size_t)n * S_LEN * HDIM;
    const unsigned short* gvh = g_vhi + (size_t)n * S_LEN * HDIM + (size_t)lrow * S_LEN;
    const unsigned short* gvl = g_vlo + (size_t)n * S_LEN * HDIM + (size_t)lrow * S_LEN;
    const uint32_t dKV = (uint32_t)(lrow * KST + lseg * 8) * 2;

#define ATT_ISSUE(KT, STG) do { \
    uint32_t dst = sbase + (uint32_t)(STG) * ATT_STAGE * 2 + dKV; \
    const unsigned short* sk = gkh + ((KT)*64 + lrow) * HDIM + lseg * 8; \
    const unsigned short* sl = gkl + ((KT)*64 + lrow) * HDIM + lseg * 8; \
    const unsigned short* sv = gvh + (KT)*64 + lseg * 8; \
    const unsigned short* sw = gvl + (KT)*64 + lseg * 8; \
    CP_ASYNC16(dst,                    sk);      CP_ASYNC16(dst + 16,                    sk + 8); \
    CP_ASYNC16(dst + 64*KST*2,         sl);      CP_ASYNC16(dst + 64*KST*2 + 16,         sl + 8); \
    CP_ASYNC16(dst + 2*64*KST*2,       sv);      CP_ASYNC16(dst + 2*64*KST*2 + 16,       sv + 8); \
    CP_ASYNC16(dst + 3*64*KST*2,       sw);      CP_ASYNC16(dst + 3*64*KST*2 + 16,       sw + 8); \
    CP_COMMIT; } while (0)

    const int bRow = (lane & 7) + ((lane >> 4) << 3);
    const int bK   = ((lane >> 3) & 1) * 8;

    ATT_ISSUE(0, 0);

    for (int kt = 0; kt < 16; kt++) {
        const int stg = kt & 1;
        CP_WAIT0;
        __syncthreads();            // single barrier per tile
        if (kt < 15) ATT_ISSUE(kt + 1, stg ^ 1);

        const uint32_t base = sbase + (uint32_t)stg * ATT_STAGE * 2;

        float sacc[8][4];
#pragma unroll
        for (int i = 0; i < 8; i++)
#pragma unroll
            for (int j = 0; j < 4; j++) sacc[i][j] = 0.f;

#pragma unroll
        for (int ks = 0; ks < 4; ks++) {
#pragma unroll
            for (int np = 0; np < 4; np++) {
                uint32_t bh[4], bl[4];
                uint32_t rb = base + (uint32_t)((np*16 + bRow) * KST + ks*16 + bK) * 2;
                ldsm_x4(bh[0], bh[1], bh[2], bh[3], rb);
                ldsm_x4(bl[0], bl[1], bl[2], bl[3], rb + 64*KST*2);
#pragma unroll
                for (int j = 0; j < 2; j++) {
                    const int ni = np * 2 + j;
                    mma16816(sacc[ni], aqh[ks], &bh[2*j]);
                    mma16816(sacc[ni], aql[ks], &bh[2*j]);
                    mma16816(sacc[ni], aqh[ks], &bl[2*j]);
                }
            }
        }

        float mx0 = -1e30f, mx1 = -1e30f;
#pragma unroll
        for (int ni = 0; ni < 8; ni++) {
            float2 mk = *(const float2*)&msm[kt*64 + ni*8 + 2*tg];
            sacc[ni][0] += mk.x; sacc[ni][1] += mk.y;
            sacc[ni][2] += mk.x; sacc[ni][3] += mk.y;
            mx0 = fmaxf(mx0, fmaxf(sacc[ni][0], sacc[ni][1]));
            mx1 = fmaxf(mx1, fmaxf(sacc[ni][2], sacc[ni][3]));
        }
        mx0 = fmaxf(mx0, __shfl_xor_sync(0xffffffffu, mx0, 1));
        mx0 = fmaxf(mx0, __shfl_xor_sync(0xffffffffu, mx0, 2));
        mx1 = fmaxf(mx1, __shfl_xor_sync(0xffffffffu, mx1, 1));
        mx1 = fmaxf(mx1, __shfl_xor_sync(0xffffffffu, mx1, 2));
        float m0n = fmaxf(m0, mx0), m1n = fmaxf(m1, mx1);
        float f0 = __expf(m0 - m0n), f1 = __expf(m1 - m1n);
        m0 = m0n; m1 = m1n;
        float s0 = 0.f, s1 = 0.f;
#pragma unroll
        for (int ni = 0; ni < 8; ni++) {
            sacc[ni][0] = __expf(sacc[ni][0] - m0n);
            sacc[ni][1] = __expf(sacc[ni][1] - m0n);
            sacc[ni][2] = __expf(sacc[ni][2] - m1n);
            sacc[ni][3] = __expf(sacc[ni][3] - m1n);
            s0 += sacc[ni][0] + sacc[ni][1];
            s1 += sacc[ni][2] + sacc[ni][3];
        }
        s0 += __shfl_xor_sync(0xffffffffu, s0, 1);
        s0 += __shfl_xor_sync(0xffffffffu, s0, 2);
        s1 += __shfl_xor_sync(0xffffffffu, s1, 1);
        s1 += __shfl_xor_sync(0xffffffffu, s1, 2);
        l0 = l0 * f0 + s0;
        l1 = l1 * f1 + s1;
#pragma unroll
        for (int ni = 0; ni < 8; ni++) {
            oacc[ni][0] *= f0; oacc[ni][1] *= f0;
            oacc[ni][2] *= f1; oacc[ni][3] *= f1;
        }

#pragma unroll
        for (int kk = 0; kk < 4; kk++) {
            uint32_t pah[4], pal[4];
            split2(sacc[2*kk][0],   sacc[2*kk][1],   pah[0], pal[0]);
            split2(sacc[2*kk][2],   sacc[2*kk][3],   pah[1], pal[1]);
            split2(sacc[2*kk+1][0], sacc[2*kk+1][1], pah[2], pal[2]);
            split2(sacc[2*kk+1][2], sacc[2*kk+1][3], pah[3], pal[3]);
#pragma unroll
            for (int np = 0; np < 4; np++) {
                uint32_t vh[4], vl[4];
                uint32_t rb = base + (uint32_t)(2*64*KST + (np*16 + bRow) * KST + kk*16 + bK) * 2;
                ldsm_x4(vh[0], vh[1], vh[2], vh[3], rb);
                ldsm_x4(vl[0], vl[1], vl[2], vl[3], rb + 64*KST*2);
#pragma unroll
                for (int j = 0; j < 2; j++) {
                    const int ni = np * 2 + j;
                    mma16816(oacc[ni], pah, &vh[2*j]);
                    mma16816(oacc[ni], pal, &vh[2*j]);
                    mma16816(oacc[ni], pah, &vl[2*j]);
                }
            }
        }
    }

    const float inv0 = 1.f / l0, inv1 = 1.f / l1;
    const int b = n >> 4, h = n & 15;
    const int row0 = qt * 128 + wid * 16 + g;
#pragma unroll
    for (int ni = 0; ni < 8; ni++) {
        int d = ni * 8 + 2 * tg;
        float2 v0 = make_float2(oacc[ni][0] * inv0, oacc[ni][1] * inv0);
        float2 v1 = make_float2(oacc[ni][2] * inv1, oacc[ni][3] * inv1);
        *(float2*)(out + (size_t)row0 * (BATCH*HID) + b * HID + h * HDIM + d) = v0;
        *(float2*)(out + (size_t)(row0 + 8) * (BATCH*HID) + b * HID + h * HDIM + d) = v1;
    }
}

// ------------------------------------------------------------------
extern "C" void kernel_launch(void* const* d_in, const int* in_sizes, int n_in,
                              void* d_out, int out_size)
{
    const float* hs   = (const float*)d_in[0];
    const float* mask = (const float*)d_in[1];
    const float* Wq   = (const float*)d_in[2];
    const float* bq   = (const float*)d_in[3];
    const float* Wk   = (const float*)d_in[4];
    const float* bk   = (const float*)d_in[5];
    const float* Wv   = (const float*)d_in[6];
    const float* bv   = (const float*)d_in[7];
    float* out = (float*)d_out;

    cvt_all<<<7168, 256>>>(hs, Wq, Wk, Wv);

    cudaFuncSetAttribute(qkv_mma, cudaFuncAttributeMaxDynamicSharedMemorySize, QKV_SMEM);
    qkv_mma<<<dim3(NTOT/128, MTOT/128), 256, QKV_SMEM>>>(bq, bk, bv);

    cudaFuncSetAttribute(attn_mma, cudaFuncAttributeMaxDynamicSharedMemorySize, ATT_SMEM);
    attn_mma<<<dim3(NH, S_LEN/128), 256, ATT_SMEM>>>(mask, out);
}

// round 6
// speedup vs baseline: 3.5487x; 1.5148x over previous
#include <cuda_runtime.h>
#include <cuda_fp16.h>
#include <cstdint>

#define S_LEN 1024
#define BATCH 4
#define HID   1024
#define NHEAD 16
#define HDIM  64
#define NH    (BATCH*NHEAD)     // 64 heads
#define MTOT  (S_LEN*BATCH)     // 4096
#define NTOT  (3*HID)           // 3072 (q|k|v stacked)

// fp16 operands: A (hidden) as hi/lo pair, W single
__device__ unsigned short g_Ahi[MTOT*HID], g_Alo[MTOT*HID];
__device__ unsigned short g_Wh[NTOT*HID];
// projections: q pair [head][s][d]; k single [head][s][d]; v single [head][d][s]
__device__ unsigned short g_qhi[NH*S_LEN*HDIM], g_qlo[NH*S_LEN*HDIM];
__device__ unsigned short g_kh[NH*S_LEN*HDIM];
__device__ unsigned short g_vh[NH*S_LEN*HDIM];

// ---------------- helpers ----------------
__device__ __forceinline__ uint32_t smem_u32(const void* p) {
    uint32_t a;
    asm("{ .reg .u64 t; cvta.to.shared.u64 t, %1; cvt.u32.u64 %0, t; }" : "=r"(a) : "l"(p));
    return a;
}
__device__ __forceinline__ void mma16816(float* c, const uint32_t* a, const uint32_t* b) {
    asm volatile("mma.sync.aligned.m16n8k16.row.col.f32.f16.f16.f32 "
        "{%0,%1,%2,%3},{%4,%5,%6,%7},{%8,%9},{%0,%1,%2,%3};"
        : "+f"(c[0]), "+f"(c[1]), "+f"(c[2]), "+f"(c[3])
        : "r"(a[0]), "r"(a[1]), "r"(a[2]), "r"(a[3]), "r"(b[0]), "r"(b[1]));
}
__device__ __forceinline__ void ldsm_x4(uint32_t& r0, uint32_t& r1, uint32_t& r2,
                                        uint32_t& r3, uint32_t addr) {
    asm volatile("ldmatrix.sync.aligned.m8n8.x4.shared.b16 {%0,%1,%2,%3}, [%4];"
        : "=r"(r0), "=r"(r1), "=r"(r2), "=r"(r3) : "r"(addr));
}
#define CP_ASYNC16(dst, src) \
    asm volatile("cp.async.cg.shared.global [%0], [%1], 16;" :: "r"(dst), "l"(src))
#define CP_COMMIT asm volatile("cp.async.commit_group;" ::: "memory")
#define CP_WAIT0  asm volatile("cp.async.wait_group 0;" ::: "memory")

// fp16 pair split
__device__ __forceinline__ void split2h(float x, float y, uint32_t& hi, uint32_t& lo) {
    __half hx = __float2half_rn(x), hy = __float2half_rn(y);
    __half lx = __float2half_rn(x - __half2float(hx));
    __half ly = __float2half_rn(y - __half2float(hy));
    hi = (uint32_t)__half_as_ushort(hx) | ((uint32_t)__half_as_ushort(hy) << 16);
    lo = (uint32_t)__half_as_ushort(lx) | ((uint32_t)__half_as_ushort(ly) << 16);
}

// ---------------- conversion: hidden -> fp16 pair, weights -> fp16 single ----------------
__global__ __launch_bounds__(256)
void cvt_all(const float* __restrict__ hs, const float* __restrict__ Wq,
             const float* __restrict__ Wk, const float* __restrict__ Wv)
{
    const int bid = blockIdx.x;
    if (bid < 4096) {
        size_t off = (size_t)bid * 1024 + threadIdx.x * 4;
        float4 x = *(const float4*)(hs + off);
        ushort4 h, l;
        __half b;
        b = __float2half_rn(x.x); h.x = __half_as_ushort(b);
        l.x = __half_as_ushort(__float2half_rn(x.x - __half2float(b)));
        b = __float2half_rn(x.y); h.y = __half_as_ushort(b);
        l.y = __half_as_ushort(__float2half_rn(x.y - __half2float(b)));
        b = __float2half_rn(x.z); h.z = __half_as_ushort(b);
        l.z = __half_as_ushort(__float2half_rn(x.z - __half2float(b)));
        b = __float2half_rn(x.w); h.w = __half_as_ushort(b);
        l.w = __half_as_ushort(__float2half_rn(x.w - __half2float(b)));
        *(ushort4*)(g_Ahi + off) = h;
        *(ushort4*)(g_Alo + off) = l;
    } else {
        int w  = (bid - 4096) >> 10;
        int lb = (bid - 4096) & 1023;
        const float* src = (w == 0) ? Wq : ((w == 1) ? Wk : Wv);
        size_t off = (size_t)lb * 1024 + threadIdx.x * 4;
        float4 x = *(const float4*)(src + off);
        ushort4 h;
        h.x = __half_as_ushort(__float2half_rn(x.x));
        h.y = __half_as_ushort(__float2half_rn(x.y));
        h.z = __half_as_ushort(__float2half_rn(x.z));
        h.w = __half_as_ushort(__float2half_rn(x.w));
        *(ushort4*)(g_Wh + (size_t)w * HID * HID + off) = h;
    }
}

// ================= QKV GEMM: 2-term (A pair x W single) =================
#define GST 40
#define QKV_STAGE (3*128*GST)        // ushorts per stage (Ah|Al|Wh)
#define QKV_SMEM  (2*QKV_STAGE*2)    // 61440 bytes
#define MST 130                      // V-transpose tile stride

__global__ __launch_bounds__(256)
void qkv_mma(const float* __restrict__ bq, const float* __restrict__ bk,
             const float* __restrict__ bv)
{
    extern __shared__ unsigned short smq[];
    const int tid = threadIdx.x, lane = tid & 31, wid = tid >> 5;
    const int wm = wid >> 2, wn = wid & 3;
    const int g = lane >> 2, tg = lane & 3;
    const int m0 = blockIdx.y * 128, c0 = blockIdx.x * 128;
    const uint32_t sbase = smem_u32(smq);

    float acc[4][4][4];
#pragma unroll
    for (int i = 0; i < 4; i++)
#pragma unroll
        for (int j = 0; j < 4; j++)
#pragma unroll
            for (int k = 0; k < 4; k++) acc[i][j][k] = 0.f;

    const int lrow = tid >> 1, lhalf = tid & 1;
    const unsigned short* gA0 = g_Ahi + (size_t)(m0 + lrow) * HID + lhalf * 16;
    const unsigned short* gA1 = g_Alo + (size_t)(m0 + lrow) * HID + lhalf * 16;
    const unsigned short* gW0 = g_Wh  + (size_t)(c0 + lrow) * HID + lhalf * 16;
    const uint32_t dOff = (uint32_t)(lrow * GST + lhalf * 16) * 2;

    const int aRow = wm * 64 + (lane & 15);
    const int aK   = (lane >> 4) * 8;
    const int bRow = wn * 32 + (lane & 7) + ((lane >> 4) << 3);
    const int bK   = ((lane >> 3) & 1) * 8;

#define QKV_ISSUE(CH, STG) do { \
    int k0 = (CH) * 32; \
    uint32_t dst = sbase + (uint32_t)(STG) * QKV_STAGE * 2 + dOff; \
    CP_ASYNC16(dst,                    gA0 + k0); \
    CP_ASYNC16(dst + 16,               gA0 + k0 + 8); \
    CP_ASYNC16(dst + 128*GST*2,        gA1 + k0); \
    CP_ASYNC16(dst + 128*GST*2 + 16,   gA1 + k0 + 8); \
    CP_ASYNC16(dst + 2*128*GST*2,      gW0 + k0); \
    CP_ASYNC16(dst + 2*128*GST*2 + 16, gW0 + k0 + 8); \
    CP_COMMIT; } while (0)

    QKV_ISSUE(0, 0);

    for (int ch = 0; ch < 32; ch++) {
        const int stg = ch & 1;
        CP_WAIT0;
        __syncthreads();
        if (ch < 31) QKV_ISSUE(ch + 1, stg ^ 1);

        const uint32_t base = sbase + (uint32_t)stg * QKV_STAGE * 2;
#pragma unroll
        for (int ks = 0; ks < 2; ks++) {
            uint32_t ah[4][4], al[4][4];
#pragma unroll
            for (int mi = 0; mi < 4; mi++) {
                uint32_t ra = base + (uint32_t)((aRow + mi*16) * GST + ks*16 + aK) * 2;
                ldsm_x4(ah[mi][0], ah[mi][1], ah[mi][2], ah[mi][3], ra);
                ldsm_x4(al[mi][0], al[mi][1], al[mi][2], al[mi][3], ra + 128*GST*2);
            }
#pragma unroll
            for (int np = 0; np < 2; np++) {
                uint32_t wh[4];
                uint32_t rb = base + (uint32_t)(2*128*GST + (bRow + np*16) * GST + ks*16 + bK) * 2;
                ldsm_x4(wh[0], wh[1], wh[2], wh[3], rb);
#pragma unroll
                for (int j = 0; j < 2; j++) {
                    const int ni = np * 2 + j;
#pragma unroll
                    for (int mi = 0; mi < 4; mi++) {
                        mma16816(acc[mi][ni], ah[mi], &wh[2*j]);
                        mma16816(acc[mi][ni], al[mi], &wh[2*j]);
                    }
                }
            }
        }
    }

    const int which = c0 >> 10;
    const float* bias = (which == 0) ? bq : ((which == 1) ? bk : bv);

    if (which == 0) {
        // Q: fp16 pair, 1/8 scale folded in
#pragma unroll
        for (int mi = 0; mi < 4; mi++) {
#pragma unroll
            for (int ni = 0; ni < 4; ni++) {
                int colE = c0 + wn * 32 + ni * 8 + 2 * tg;
                int bcol = colE & 1023;
                float b0f = bias[bcol], b1f = bias[bcol + 1];
                int hh = (colE >> 6) & 15, dd = colE & 63;
#pragma unroll
                for (int hr = 0; hr < 2; hr++) {
                    int row = m0 + wm * 64 + mi * 16 + g + hr * 8;
                    int s = row >> 2, b = row & 3;
                    float x = (acc[mi][ni][hr * 2 + 0] + b0f) * 0.125f;
                    float y = (acc[mi][ni][hr * 2 + 1] + b1f) * 0.125f;
                    uint32_t hi, lo;
                    split2h(x, y, hi, lo);
                    size_t idx = ((size_t)(b * NHEAD + hh) * S_LEN + s) * HDIM + dd;
                    *(uint32_t*)&g_qhi[idx] = hi;
                    *(uint32_t*)&g_qlo[idx] = lo;
                }
            }
        }
    } else if (which == 1) {
        // K: fp16 single
#pragma unroll
        for (int mi = 0; mi < 4; mi++) {
#pragma unroll
            for (int ni = 0; ni < 4; ni++) {
                int colE = c0 + wn * 32 + ni * 8 + 2 * tg;
                int bcol = colE & 1023;
                float b0f = bias[bcol], b1f = bias[bcol + 1];
                int hh = (colE >> 6) & 15, dd = colE & 63;
#pragma unroll
                for (int hr = 0; hr < 2; hr++) {
                    int row = m0 + wm * 64 + mi * 16 + g + hr * 8;
                    int s = row >> 2, b = row & 3;
                    __half hx = __float2half_rn(acc[mi][ni][hr * 2 + 0] + b0f);
                    __half hy = __float2half_rn(acc[mi][ni][hr * 2 + 1] + b1f);
                    uint32_t hv = (uint32_t)__half_as_ushort(hx)
                                | ((uint32_t)__half_as_ushort(hy) << 16);
                    size_t idx = ((size_t)(b * NHEAD + hh) * S_LEN + s) * HDIM + dd;
                    *(uint32_t*)&g_kh[idx] = hv;
                }
            }
        }
    } else {
        // V: fp16 single, transpose through smem -> [head][d][s]
        unsigned short* Th = smq;
        __syncthreads();
#pragma unroll
        for (int mi = 0; mi < 4; mi++) {
#pragma unroll
            for (int ni = 0; ni < 4; ni++) {
                int col = wn * 32 + ni * 8 + 2 * tg;
                int bcol = (c0 + col) & 1023;
                float b0f = bias[bcol], b1f = bias[bcol + 1];
#pragma unroll
                for (int hr = 0; hr < 2; hr++) {
                    int rloc = wm * 64 + mi * 16 + g + hr * 8;
                    Th[col * MST + rloc]       = __half_as_ushort(
                        __float2half_rn(acc[mi][ni][hr * 2 + 0] + b0f));
                    Th[(col + 1) * MST + rloc] = __half_as_ushort(
                        __float2half_rn(acc[mi][ni][hr * 2 + 1] + b1f));
                }
            }
        }
        __syncthreads();
#pragma unroll
        for (int rep = 0; rep < 2; rep++) {
            int sid = tid + rep * 256;
            int col = sid >> 2, b = sid & 3;
            int cg = c0 + col;
            int hh = (cg >> 6) & 15, dd = cg & 63;
            size_t gb = ((size_t)(b * NHEAD + hh) * HDIM + dd) * S_LEN + (m0 >> 2);
            uint32_t uh[16];
#pragma unroll
            for (int j = 0; j < 16; j++) {
                uh[j] = (uint32_t)Th[col * MST + (2*j) * 4 + b]
                      | ((uint32_t)Th[col * MST + (2*j + 1) * 4 + b] << 16);
            }
#pragma unroll
            for (int j = 0; j < 4; j++)
                *(uint4*)(g_vh + gb + j * 8) = make_uint4(uh[4*j], uh[4*j+1], uh[4*j+2], uh[4*j+3]);
        }
    }
}

// ================= flash attention: 2-term (Q/P pair x K/V single) =================
#define KST 72
#define ATT_STAGE (2*64*KST)         // ushorts per stage (Kh|Vh)
#define ATT_SMEM (2*ATT_STAGE*2 + S_LEN*4)

__global__ __launch_bounds__(256)
void attn_mma(const float* __restrict__ mask, float* __restrict__ out)
{
    extern __shared__ unsigned short sma[];
    float* msm = (float*)(sma + 2 * ATT_STAGE);
    const int n = blockIdx.x, qt = blockIdx.y;
    const int tid = threadIdx.x, lane = tid & 31, wid = tid >> 5;
    const int g = lane >> 2, tg = lane & 3;
    const uint32_t sbase = smem_u32(sma);

    *(float4*)&msm[tid * 4] = *(const float4*)(mask + (size_t)n * S_LEN + tid * 4);

    uint32_t aqh[4][4], aql[4][4];
    {
        const int row = qt * 128 + wid * 16 + g;
        const unsigned short* qh = g_qhi + ((size_t)n * S_LEN + row) * HDIM;
        const unsigned short* ql = g_qlo + ((size_t)n * S_LEN + row) * HDIM;
#pragma unroll
        for (int ks = 0; ks < 4; ks++) {
            int k = ks * 16 + 2 * tg;
            aqh[ks][0] = *(const uint32_t*)(qh + k);
            aqh[ks][1] = *(const uint32_t*)(qh + 8*HDIM + k);
            aqh[ks][2] = *(const uint32_t*)(qh + k + 8);
            aqh[ks][3] = *(const uint32_t*)(qh + 8*HDIM + k + 8);
            aql[ks][0] = *(const uint32_t*)(ql + k);
            aql[ks][1] = *(const uint32_t*)(ql + 8*HDIM + k);
            aql[ks][2] = *(const uint32_t*)(ql + k + 8);
            aql[ks][3] = *(const uint32_t*)(ql + 8*HDIM + k + 8);
        }
    }

    float oacc[8][4];
#pragma unroll
    for (int i = 0; i < 8; i++)
#pragma unroll
        for (int j = 0; j < 4; j++) oacc[i][j] = 0.f;
    float m0 = -1e30f, m1 = -1e30f, l0 = 0.f, l1 = 0.f;

    const int lrow = tid >> 2, lseg = (tid & 3) * 2;
    const unsigned short* gkh = g_kh + (size_t)n * S_LEN * HDIM;
    const unsigned short* gvh = g_vh + (size_t)n * S_LEN * HDIM + (size_t)lrow * S_LEN;
    const uint32_t dKV = (uint32_t)(lrow * KST + lseg * 8) * 2;

#define ATT_ISSUE(KT, STG) do { \
    uint32_t dst = sbase + (uint32_t)(STG) * ATT_STAGE * 2 + dKV; \
    const unsigned short* sk = gkh + ((KT)*64 + lrow) * HDIM + lseg * 8; \
    const unsigned short* sv = gvh + (KT)*64 + lseg * 8; \
    CP_ASYNC16(dst,              sk);  CP_ASYNC16(dst + 16,              sk + 8); \
    CP_ASYNC16(dst + 64*KST*2,   sv);  CP_ASYNC16(dst + 64*KST*2 + 16,   sv + 8); \
    CP_COMMIT; } while (0)

    const int bRow = (lane & 7) + ((lane >> 4) << 3);
    const int bK   = ((lane >> 3) & 1) * 8;

    ATT_ISSUE(0, 0);

    for (int kt = 0; kt < 16; kt++) {
        const int stg = kt & 1;
        CP_WAIT0;
        __syncthreads();
        if (kt < 15) ATT_ISSUE(kt + 1, stg ^ 1);

        const uint32_t base = sbase + (uint32_t)stg * ATT_STAGE * 2;

        float sacc[8][4];
#pragma unroll
        for (int i = 0; i < 8; i++)
#pragma unroll
            for (int j = 0; j < 4; j++) sacc[i][j] = 0.f;

#pragma unroll
        for (int ks = 0; ks < 4; ks++) {
#pragma unroll
            for (int np = 0; np < 4; np++) {
                uint32_t kh[4];
                uint32_t rb = base + (uint32_t)((np*16 + bRow) * KST + ks*16 + bK) * 2;
                ldsm_x4(kh[0], kh[1], kh[2], kh[3], rb);
#pragma unroll
                for (int j = 0; j < 2; j++) {
                    const int ni = np * 2 + j;
                    mma16816(sacc[ni], aqh[ks], &kh[2*j]);
                    mma16816(sacc[ni], aql[ks], &kh[2*j]);
                }
            }
        }

        float mx0 = -1e30f, mx1 = -1e30f;
#pragma unroll
        for (int ni = 0; ni < 8; ni++) {
            float2 mk = *(const float2*)&msm[kt*64 + ni*8 + 2*tg];
            sacc[ni][0] += mk.x; sacc[ni][1] += mk.y;
            sacc[ni][2] += mk.x; sacc[ni][3] += mk.y;
            mx0 = fmaxf(mx0, fmaxf(sacc[ni][0], sacc[ni][1]));
            mx1 = fmaxf(mx1, fmaxf(sacc[ni][2], sacc[ni][3]));
        }
        mx0 = fmaxf(mx0, __shfl_xor_sync(0xffffffffu, mx0, 1));
        mx0 = fmaxf(mx0, __shfl_xor_sync(0xffffffffu, mx0, 2));
        mx1 = fmaxf(mx1, __shfl_xor_sync(0xffffffffu, mx1, 1));
        mx1 = fmaxf(mx1, __shfl_xor_sync(0xffffffffu, mx1, 2));
        float m0n = fmaxf(m0, mx0), m1n = fmaxf(m1, mx1);
        float f0 = __expf(m0 - m0n), f1 = __expf(m1 - m1n);
        m0 = m0n; m1 = m1n;
        float s0 = 0.f, s1 = 0.f;
#pragma unroll
        for (int ni = 0; ni < 8; ni++) {
            sacc[ni][0] = __expf(sacc[ni][0] - m0n);
            sacc[ni][1] = __expf(sacc[ni][1] - m0n);
            sacc[ni][2] = __expf(sacc[ni][2] - m1n);
            sacc[ni][3] = __expf(sacc[ni][3] - m1n);
            s0 += sacc[ni][0] + sacc[ni][1];
            s1 += sacc[ni][2] + sacc[ni][3];
        }
        s0 += __shfl_xor_sync(0xffffffffu, s0, 1);
        s0 += __shfl_xor_sync(0xffffffffu, s0, 2);
        s1 += __shfl_xor_sync(0xffffffffu, s1, 1);
        s1 += __shfl_xor_sync(0xffffffffu, s1, 2);
        l0 = l0 * f0 + s0;
        l1 = l1 * f1 + s1;
#pragma unroll
        for (int ni = 0; ni < 8; ni++) {
            oacc[ni][0] *= f0; oacc[ni][1] *= f0;
            oacc[ni][2] *= f1; oacc[ni][3] *= f1;
        }

        // AV: P pair (registers) x V single
#pragma unroll
        for (int kk = 0; kk < 4; kk++) {
            uint32_t pah[4], pal[4];
            split2h(sacc[2*kk][0],   sacc[2*kk][1],   pah[0], pal[0]);
            split2h(sacc[2*kk][2],   sacc[2*kk][3],   pah[1], pal[1]);
            split2h(sacc[2*kk+1][0], sacc[2*kk+1][1], pah[2], pal[2]);
            split2h(sacc[2*kk+1][2], sacc[2*kk+1][3], pah[3], pal[3]);
#pragma unroll
            for (int np = 0; np < 4; np++) {
                uint32_t vh[4];
                uint32_t rb = base + (uint32_t)(64*KST + (np*16 + bRow) * KST + kk*16 + bK) * 2;
                ldsm_x4(vh[0], vh[1], vh[2], vh[3], rb);
#pragma unroll
                for (int j = 0; j < 2; j++) {
                    const int ni = np * 2 + j;
                    mma16816(oacc[ni], pah, &vh[2*j]);
                    mma16816(oacc[ni], pal, &vh[2*j]);
                }
            }
        }
    }

    const float inv0 = 1.f / l0, inv1 = 1.f / l1;
    const int b = n >> 4, h = n & 15;
    const int row0 = qt * 128 + wid * 16 + g;
#pragma unroll
    for (int ni = 0; ni < 8; ni++) {
        int d = ni * 8 + 2 * tg;
        float2 v0 = make_float2(oacc[ni][0] * inv0, oacc[ni][1] * inv0);
        float2 v1 = make_float2(oacc[ni][2] * inv1, oacc[ni][3] * inv1);
        *(float2*)(out + (size_t)row0 * (BATCH*HID) + b * HID + h * HDIM + d) = v0;
        *(float2*)(out + (size_t)(row0 + 8) * (BATCH*HID) + b * HID + h * HDIM + d) = v1;
    }
}

// ------------------------------------------------------------------
extern "C" void kernel_launch(void* const* d_in, const int* in_sizes, int n_in,
                              void* d_out, int out_size)
{
    const float* hs   = (const float*)d_in[0];
    const float* mask = (const float*)d_in[1];
    const float* Wq   = (const float*)d_in[2];
    const float* bq   = (const float*)d_in[3];
    const float* Wk   = (const float*)d_in[4];
    const float* bk   = (const float*)d_in[5];
    const float* Wv   = (const float*)d_in[6];
    const float* bv   = (const float*)d_in[7];
    float* out = (float*)d_out;

    cvt_all<<<7168, 256>>>(hs, Wq, Wk, Wv);

    cudaFuncSetAttribute(qkv_mma, cudaFuncAttributeMaxDynamicSharedMemorySize, QKV_SMEM);
    qkv_mma<<<dim3(NTOT/128, MTOT/128), 256, QKV_SMEM>>>(bq, bk, bv);

    cudaFuncSetAttribute(attn_mma, cudaFuncAttributeMaxDynamicSharedMemorySize, ATT_SMEM);
    attn_mma<<<dim3(NH, S_LEN/128), 256, ATT_SMEM>>>(mask, out);
}

// round 7
// speedup vs baseline: 6.0095x; 1.6934x over previous
#include <cuda_runtime.h>
#include <cuda_fp16.h>
#include <cstdint>

#define S_LEN 1024
#define BATCH 4
#define HID   1024
#define NHEAD 16
#define HDIM  64
#define NH    (BATCH*NHEAD)     // 64 heads
#define MTOT  (S_LEN*BATCH)     // 4096
#define NTOT  (3*HID)           // 3072 (q|k|v stacked)

// fp16 single operands everywhere
__device__ unsigned short g_Ah[MTOT*HID];
__device__ unsigned short g_Wh[NTOT*HID];
// projections: q,k [head][s][d]; v [head][d][s] (transposed)
__device__ unsigned short g_qh[NH*S_LEN*HDIM];
__device__ unsigned short g_kh[NH*S_LEN*HDIM];
__device__ unsigned short g_vh[NH*S_LEN*HDIM];

// ---------------- helpers ----------------
__device__ __forceinline__ uint32_t smem_u32(const void* p) {
    uint32_t a;
    asm("{ .reg .u64 t; cvta.to.shared.u64 t, %1; cvt.u32.u64 %0, t; }" : "=r"(a) : "l"(p));
    return a;
}
__device__ __forceinline__ void mma16816(float* c, const uint32_t* a, const uint32_t* b) {
    asm volatile("mma.sync.aligned.m16n8k16.row.col.f32.f16.f16.f32 "
        "{%0,%1,%2,%3},{%4,%5,%6,%7},{%8,%9},{%0,%1,%2,%3};"
        : "+f"(c[0]), "+f"(c[1]), "+f"(c[2]), "+f"(c[3])
        : "r"(a[0]), "r"(a[1]), "r"(a[2]), "r"(a[3]), "r"(b[0]), "r"(b[1]));
}
__device__ __forceinline__ void ldsm_x4(uint32_t& r0, uint32_t& r1, uint32_t& r2,
                                        uint32_t& r3, uint32_t addr) {
    asm volatile("ldmatrix.sync.aligned.m8n8.x4.shared.b16 {%0,%1,%2,%3}, [%4];"
        : "=r"(r0), "=r"(r1), "=r"(r2), "=r"(r3) : "r"(addr));
}
#define CP_ASYNC16(dst, src) \
    asm volatile("cp.async.cg.shared.global [%0], [%1], 16;" :: "r"(dst), "l"(src))
#define CP_COMMIT asm volatile("cp.async.commit_group;" ::: "memory")
#define CP_WAIT0  asm volatile("cp.async.wait_group 0;" ::: "memory")

__device__ __forceinline__ uint32_t pack2h(float x, float y) {
    __half2 h = __floats2half2_rn(x, y);
    return *(uint32_t*)&h;
}

// ---------------- conversion: everything -> single fp16 ----------------
__global__ __launch_bounds__(256)
void cvt_all(const float* __restrict__ hs, const float* __restrict__ Wq,
             const float* __restrict__ Wk, const float* __restrict__ Wv)
{
    const int bid = blockIdx.x;
    const float* src;
    unsigned short* dst;
    size_t off;
    if (bid < 4096) {
        src = hs; dst = g_Ah;
        off = (size_t)bid * 1024 + threadIdx.x * 4;
    } else {
        int w  = (bid - 4096) >> 10;
        int lb = (bid - 4096) & 1023;
        src = (w == 0) ? Wq : ((w == 1) ? Wk : Wv);
        dst = g_Wh + (size_t)w * HID * HID;
        off = (size_t)lb * 1024 + threadIdx.x * 4;
    }
    float4 x = *(const float4*)(src + off);
    ushort4 h;
    h.x = __half_as_ushort(__float2half_rn(x.x));
    h.y = __half_as_ushort(__float2half_rn(x.y));
    h.z = __half_as_ushort(__float2half_rn(x.z));
    h.w = __half_as_ushort(__float2half_rn(x.w));
    *(ushort4*)(dst + off) = h;
}

// ================= QKV GEMM: single fp16 =================
#define GST 40
#define QKV_STAGE (2*128*GST)        // ushorts per stage (A|W)
#define QKV_SMEM  (2*QKV_STAGE*2)    // 40960 bytes
#define MST 130                      // V-transpose tile stride

__global__ __launch_bounds__(256)
void qkv_mma(const float* __restrict__ bq, const float* __restrict__ bk,
             const float* __restrict__ bv)
{
    extern __shared__ unsigned short smq[];
    const int tid = threadIdx.x, lane = tid & 31, wid = tid >> 5;
    const int wm = wid >> 2, wn = wid & 3;
    const int g = lane >> 2, tg = lane & 3;
    const int m0 = blockIdx.y * 128, c0 = blockIdx.x * 128;
    const uint32_t sbase = smem_u32(smq);

    float acc[4][4][4];
#pragma unroll
    for (int i = 0; i < 4; i++)
#pragma unroll
        for (int j = 0; j < 4; j++)
#pragma unroll
            for (int k = 0; k < 4; k++) acc[i][j][k] = 0.f;

    const int lrow = tid >> 1, lhalf = tid & 1;
    const unsigned short* gA0 = g_Ah + (size_t)(m0 + lrow) * HID + lhalf * 16;
    const unsigned short* gW0 = g_Wh + (size_t)(c0 + lrow) * HID + lhalf * 16;
    const uint32_t dOff = (uint32_t)(lrow * GST + lhalf * 16) * 2;

    const int aRow = wm * 64 + (lane & 15);
    const int aK   = (lane >> 4) * 8;
    const int bRow = wn * 32 + (lane & 7) + ((lane >> 4) << 3);
    const int bK   = ((lane >> 3) & 1) * 8;

#define QKV_ISSUE(CH, STG) do { \
    int k0 = (CH) * 32; \
    uint32_t dst = sbase + (uint32_t)(STG) * QKV_STAGE * 2 + dOff; \
    CP_ASYNC16(dst,                  gA0 + k0); \
    CP_ASYNC16(dst + 16,             gA0 + k0 + 8); \
    CP_ASYNC16(dst + 128*GST*2,      gW0 + k0); \
    CP_ASYNC16(dst + 128*GST*2 + 16, gW0 + k0 + 8); \
    CP_COMMIT; } while (0)

    QKV_ISSUE(0, 0);

    for (int ch = 0; ch < 32; ch++) {
        const int stg = ch & 1;
        CP_WAIT0;
        __syncthreads();
        if (ch < 31) QKV_ISSUE(ch + 1, stg ^ 1);

        const uint32_t base = sbase + (uint32_t)stg * QKV_STAGE * 2;
#pragma unroll
        for (int ks = 0; ks < 2; ks++) {
            uint32_t ah[4][4];
#pragma unroll
            for (int mi = 0; mi < 4; mi++) {
                uint32_t ra = base + (uint32_t)((aRow + mi*16) * GST + ks*16 + aK) * 2;
                ldsm_x4(ah[mi][0], ah[mi][1], ah[mi][2], ah[mi][3], ra);
            }
#pragma unroll
            for (int np = 0; np < 2; np++) {
                uint32_t wh[4];
                uint32_t rb = base + (uint32_t)(128*GST + (bRow + np*16) * GST + ks*16 + bK) * 2;
                ldsm_x4(wh[0], wh[1], wh[2], wh[3], rb);
#pragma unroll
                for (int j = 0; j < 2; j++) {
                    const int ni = np * 2 + j;
#pragma unroll
                    for (int mi = 0; mi < 4; mi++)
                        mma16816(acc[mi][ni], ah[mi], &wh[2*j]);
                }
            }
        }
    }

    const int which = c0 >> 10;
    const float* bias = (which == 0) ? bq : ((which == 1) ? bk : bv);
    const float qsc = (which == 0) ? 0.125f : 1.0f;

    if (which < 2) {
        // Q (scaled) / K: single fp16 scatter
        unsigned short* outp = (which == 0) ? g_qh : g_kh;
#pragma unroll
        for (int mi = 0; mi < 4; mi++) {
#pragma unroll
            for (int ni = 0; ni < 4; ni++) {
                int colE = c0 + wn * 32 + ni * 8 + 2 * tg;
                int bcol = colE & 1023;
                float b0f = bias[bcol], b1f = bias[bcol + 1];
                int hh = (colE >> 6) & 15, dd = colE & 63;
#pragma unroll
                for (int hr = 0; hr < 2; hr++) {
                    int row = m0 + wm * 64 + mi * 16 + g + hr * 8;
                    int s = row >> 2, b = row & 3;
                    uint32_t hv = pack2h((acc[mi][ni][hr*2+0] + b0f) * qsc,
                                         (acc[mi][ni][hr*2+1] + b1f) * qsc);
                    size_t idx = ((size_t)(b * NHEAD + hh) * S_LEN + s) * HDIM + dd;
                    *(uint32_t*)&outp[idx] = hv;
                }
            }
        }
    } else {
        // V: transpose through smem, then coalesced [head][d][s] writes
        unsigned short* Th = smq;
        __syncthreads();
#pragma unroll
        for (int mi = 0; mi < 4; mi++) {
#pragma unroll
            for (int ni = 0; ni < 4; ni++) {
                int col = wn * 32 + ni * 8 + 2 * tg;
                int bcol = (c0 + col) & 1023;
                float b0f = bias[bcol], b1f = bias[bcol + 1];
#pragma unroll
                for (int hr = 0; hr < 2; hr++) {
                    int rloc = wm * 64 + mi * 16 + g + hr * 8;
                    Th[col * MST + rloc]       = __half_as_ushort(
                        __float2half_rn(acc[mi][ni][hr * 2 + 0] + b0f));
                    Th[(col + 1) * MST + rloc] = __half_as_ushort(
                        __float2half_rn(acc[mi][ni][hr * 2 + 1] + b1f));
                }
            }
        }
        __syncthreads();
#pragma unroll
        for (int rep = 0; rep < 2; rep++) {
            int sid = tid + rep * 256;
            int col = sid >> 2, b = sid & 3;
            int cg = c0 + col;
            int hh = (cg >> 6) & 15, dd = cg & 63;
            size_t gb = ((size_t)(b * NHEAD + hh) * HDIM + dd) * S_LEN + (m0 >> 2);
            uint32_t uh[16];
#pragma unroll
            for (int j = 0; j < 16; j++) {
                uh[j] = (uint32_t)Th[col * MST + (2*j) * 4 + b]
                      | ((uint32_t)Th[col * MST + (2*j + 1) * 4 + b] << 16);
            }
#pragma unroll
            for (int j = 0; j < 4; j++)
                *(uint4*)(g_vh + gb + j * 8) = make_uint4(uh[4*j], uh[4*j+1], uh[4*j+2], uh[4*j+3]);
        }
    }
}

// ================= flash attention: single fp16 =================
#define KST 72
#define ATT_STAGE (2*64*KST)         // ushorts per stage (K|V)
#define ATT_SMEM (2*ATT_STAGE*2 + S_LEN*4)

__global__ __launch_bounds__(256)
void attn_mma(const float* __restrict__ mask, float* __restrict__ out)
{
    extern __shared__ unsigned short sma[];
    float* msm = (float*)(sma + 2 * ATT_STAGE);
    const int n = blockIdx.x, qt = blockIdx.y;
    const int tid = threadIdx.x, lane = tid & 31, wid = tid >> 5;
    const int g = lane >> 2, tg = lane & 3;
    const uint32_t sbase = smem_u32(sma);

    *(float4*)&msm[tid * 4] = *(const float4*)(mask + (size_t)n * S_LEN + tid * 4);

    // Q fragments (single fp16, 1/8 scale already folded)
    uint32_t aqh[4][4];
    {
        const int row = qt * 128 + wid * 16 + g;
        const unsigned short* qh = g_qh + ((size_t)n * S_LEN + row) * HDIM;
#pragma unroll
        for (int ks = 0; ks < 4; ks++) {
            int k = ks * 16 + 2 * tg;
            aqh[ks][0] = *(const uint32_t*)(qh + k);
            aqh[ks][1] = *(const uint32_t*)(qh + 8*HDIM + k);
            aqh[ks][2] = *(const uint32_t*)(qh + k + 8);
            aqh[ks][3] = *(const uint32_t*)(qh + 8*HDIM + k + 8);
        }
    }

    float oacc[8][4];
#pragma unroll
    for (int i = 0; i < 8; i++)
#pragma unroll
        for (int j = 0; j < 4; j++) oacc[i][j] = 0.f;
    float m0 = -1e30f, m1 = -1e30f, l0 = 0.f, l1 = 0.f;

    const int lrow = tid >> 2, lseg = (tid & 3) * 2;
    const unsigned short* gkh = g_kh + (size_t)n * S_LEN * HDIM;
    const unsigned short* gvh = g_vh + (size_t)n * S_LEN * HDIM + (size_t)lrow * S_LEN;
    const uint32_t dKV = (uint32_t)(lrow * KST + lseg * 8) * 2;

#define ATT_ISSUE(KT, STG) do { \
    uint32_t dst = sbase + (uint32_t)(STG) * ATT_STAGE * 2 + dKV; \
    const unsigned short* sk = gkh + ((KT)*64 + lrow) * HDIM + lseg * 8; \
    const unsigned short* sv = gvh + (KT)*64 + lseg * 8; \
    CP_ASYNC16(dst,              sk);  CP_ASYNC16(dst + 16,              sk + 8); \
    CP_ASYNC16(dst + 64*KST*2,   sv);  CP_ASYNC16(dst + 64*KST*2 + 16,   sv + 8); \
    CP_COMMIT; } while (0)

    const int bRow = (lane & 7) + ((lane >> 4) << 3);
    const int bK   = ((lane >> 3) & 1) * 8;

    ATT_ISSUE(0, 0);

    for (int kt = 0; kt < 16; kt++) {
        const int stg = kt & 1;
        CP_WAIT0;
        __syncthreads();
        if (kt < 15) ATT_ISSUE(kt + 1, stg ^ 1);

        const uint32_t base = sbase + (uint32_t)stg * ATT_STAGE * 2;

        float sacc[8][4];
#pragma unroll
        for (int i = 0; i < 8; i++)
#pragma unroll
            for (int j = 0; j < 4; j++) sacc[i][j] = 0.f;

#pragma unroll
        for (int ks = 0; ks < 4; ks++) {
#pragma unroll
            for (int np = 0; np < 4; np++) {
                uint32_t kh[4];
                uint32_t rb = base + (uint32_t)((np*16 + bRow) * KST + ks*16 + bK) * 2;
                ldsm_x4(kh[0], kh[1], kh[2], kh[3], rb);
                mma16816(sacc[np*2],   aqh[ks], &kh[0]);
                mma16816(sacc[np*2+1], aqh[ks], &kh[2]);
            }
        }

        float mx0 = -1e30f, mx1 = -1e30f;
#pragma unroll
        for (int ni = 0; ni < 8; ni++) {
            float2 mk = *(const float2*)&msm[kt*64 + ni*8 + 2*tg];
            sacc[ni][0] += mk.x; sacc[ni][1] += mk.y;
            sacc[ni][2] += mk.x; sacc[ni][3] += mk.y;
            mx0 = fmaxf(mx0, fmaxf(sacc[ni][0], sacc[ni][1]));
            mx1 = fmaxf(mx1, fmaxf(sacc[ni][2], sacc[ni][3]));
        }
        mx0 = fmaxf(mx0, __shfl_xor_sync(0xffffffffu, mx0, 1));
        mx0 = fmaxf(mx0, __shfl_xor_sync(0xffffffffu, mx0, 2));
        mx1 = fmaxf(mx1, __shfl_xor_sync(0xffffffffu, mx1, 1));
        mx1 = fmaxf(mx1, __shfl_xor_sync(0xffffffffu, mx1, 2));
        float m0n = fmaxf(m0, mx0), m1n = fmaxf(m1, mx1);
        float f0 = __expf(m0 - m0n), f1 = __expf(m1 - m1n);
        m0 = m0n; m1 = m1n;
        float s0 = 0.f, s1 = 0.f;
#pragma unroll
        for (int ni = 0; ni < 8; ni++) {
            sacc[ni][0] = __expf(sacc[ni][0] - m0n);
            sacc[ni][1] = __expf(sacc[ni][1] - m0n);
            sacc[ni][2] = __expf(sacc[ni][2] - m1n);
            sacc[ni][3] = __expf(sacc[ni][3] - m1n);
            s0 += sacc[ni][0] + sacc[ni][1];
            s1 += sacc[ni][2] + sacc[ni][3];
        }
        s0 += __shfl_xor_sync(0xffffffffu, s0, 1);
        s0 += __shfl_xor_sync(0xffffffffu, s0, 2);
        s1 += __shfl_xor_sync(0xffffffffu, s1, 1);
        s1 += __shfl_xor_sync(0xffffffffu, s1, 2);
        l0 = l0 * f0 + s0;
        l1 = l1 * f1 + s1;
#pragma unroll
        for (int ni = 0; ni < 8; ni++) {
            oacc[ni][0] *= f0; oacc[ni][1] *= f0;
            oacc[ni][2] *= f1; oacc[ni][3] *= f1;
        }

        // AV: P single (registers) x V single
#pragma unroll
        for (int kk = 0; kk < 4; kk++) {
            uint32_t pah[4];
            pah[0] = pack2h(sacc[2*kk][0],   sacc[2*kk][1]);
            pah[1] = pack2h(sacc[2*kk][2],   sacc[2*kk][3]);
            pah[2] = pack2h(sacc[2*kk+1][0], sacc[2*kk+1][1]);
            pah[3] = pack2h(sacc[2*kk+1][2], sacc[2*kk+1][3]);
#pragma unroll
            for (int np = 0; np < 4; np++) {
                uint32_t vh[4];
                uint32_t rb = base + (uint32_t)(64*KST + (np*16 + bRow) * KST + kk*16 + bK) * 2;
                ldsm_x4(vh[0], vh[1], vh[2], vh[3], rb);
                mma16816(oacc[np*2],   pah, &vh[0]);
                mma16816(oacc[np*2+1], pah, &vh[2]);
            }
        }
    }

    const float inv0 = 1.f / l0, inv1 = 1.f / l1;
    const int b = n >> 4, h = n & 15;
    const int row0 = qt * 128 + wid * 16 + g;
#pragma unroll
    for (int ni = 0; ni < 8; ni++) {
        int d = ni * 8 + 2 * tg;
        float2 v0 = make_float2(oacc[ni][0] * inv0, oacc[ni][1] * inv0);
        float2 v1 = make_float2(oacc[ni][2] * inv1, oacc[ni][3] * inv1);
        *(float2*)(out + (size_t)row0 * (BATCH*HID) + b * HID + h * HDIM + d) = v0;
        *(float2*)(out + (size_t)(row0 + 8) * (BATCH*HID) + b * HID + h * HDIM + d) = v1;
    }
}

// ------------------------------------------------------------------
extern "C" void kernel_launch(void* const* d_in, const int* in_sizes, int n_in,
                              void* d_out, int out_size)
{
    const float* hs   = (const float*)d_in[0];
    const float* mask = (const float*)d_in[1];
    const float* Wq   = (const float*)d_in[2];
    const float* bq   = (const float*)d_in[3];
    const float* Wk   = (const float*)d_in[4];
    const float* bk   = (const float*)d_in[5];
    const float* Wv   = (const float*)d_in[6];
    const float* bv   = (const float*)d_in[7];
    float* out = (float*)d_out;

    cvt_all<<<7168, 256>>>(hs, Wq, Wk, Wv);

    cudaFuncSetAttribute(qkv_mma, cudaFuncAttributeMaxDynamicSharedMemorySize, QKV_SMEM);
    qkv_mma<<<dim3(NTOT/128, MTOT/128), 256, QKV_SMEM>>>(bq, bk, bv);

    cudaFuncSetAttribute(attn_mma, cudaFuncAttributeMaxDynamicSharedMemorySize, ATT_SMEM);
    attn_mma<<<dim3(NH, S_LEN/128), 256, ATT_SMEM>>>(mask, out);
}